// round 8
// baseline (speedup 1.0000x reference)
#include <cuda_runtime.h>
#include <cuda_bf16.h>
#include <math.h>
#include <stdint.h>

// Problem constants
#define Bc   32
#define Nn   256
#define Hh   1024
#define HEADS 8
#define NHID 128
#define NCLS 7
#define BAND 24
#define ROWS (Bc*Nn)          // 8192
#define ALPHA_LRELU 0.2f
#define NTILES 8              // 1024/128 column tiles

typedef __nv_bfloat16 bf16;

// ---------------- device scratch (no allocs allowed) ----------------
__device__ float g_Wh[ROWS*Hh];
__device__ float g_Wh2[ROWS*Hh];
__device__ float g_s1[ROWS*HEADS];
__device__ float g_s2[ROWS*HEADS];
__device__ float g_s1b[ROWS];
__device__ float g_s2b[ROWS];
__device__ float g_mean1[Bc*Hh];
__device__ float g_loggat[ROWS*NCLS];
__device__ float g_Bprob[ROWS*NCLS];
__device__ float g_loghmm[ROWS*NCLS];
__device__ float g_blocksums[32];
// bf16 operands
__device__ bf16 g_hid_cls_bf[ROWS*Hh];
__device__ bf16 g_hid_emo_bf[ROWS*Hh];
__device__ bf16 g_fea_cls_bf[ROWS*Hh];
__device__ bf16 g_h1_bf[ROWS*Hh];
__device__ bf16 g_poolWt[Hh*Hh];   // [N][K] k-major
__device__ bf16 g_Wgt[Hh*Hh];
__device__ bf16 g_outWt[Hh*Hh];
// folded classifier tables ([7][1024] row-major)
__device__ float g_U0t[NCLS*Hh];
__device__ float g_U1t[NCLS*Hh];
__device__ float g_U2t[NCLS*Hh];
__device__ float g_Uet[NCLS*Hh];
__device__ float g_cvec[NCLS];
// split-K partial projections [ct][n][7]
__device__ float g_part_u0[NTILES*ROWS*NCLS];
__device__ float g_part_u2f[NTILES*ROWS*NCLS];
__device__ float g_part_cls[NTILES*ROWS*NCLS];
__device__ float g_part_att2[NTILES*ROWS*NCLS];

// =================== bf16 mma.sync GEMM (4-stage cp.async pipeline) ==========
#define BM 128
#define BN 128
#define BKg 32
#define GSTG 4
#define APITCH 40                             // halves per smem row (80 B)
#define STAGE_BYTES (2 * BM * APITCH * 2)     // A + B = 20480 B
#define GEMM_SMEM (GSTG * STAGE_BYTES)        // 81920 B

__device__ __forceinline__ uint32_t smem_u32(const void* p) {
    uint32_t a;
    asm("{ .reg .u64 t; cvta.to.shared.u64 t, %1; cvt.u32.u64 %0, t; }" : "=r"(a) : "l"(p));
    return a;
}
__device__ __forceinline__ void cp16(uint32_t s, const void* g) {
    asm volatile("cp.async.cg.shared.global [%0], [%1], 16;" :: "r"(s), "l"(g));
}
#define CP_COMMIT() asm volatile("cp.async.commit_group;" ::: "memory")
#define CP_WAIT2()  asm volatile("cp.async.wait_group 2;" ::: "memory")

__device__ __forceinline__ void ldsm4(uint32_t& r0, uint32_t& r1, uint32_t& r2, uint32_t& r3,
                                      uint32_t addr) {
    asm volatile("ldmatrix.sync.aligned.m8n8.x4.shared.b16 {%0,%1,%2,%3}, [%4];"
                 : "=r"(r0), "=r"(r1), "=r"(r2), "=r"(r3) : "r"(addr));
}
__device__ __forceinline__ void mma_bf16(float& d0, float& d1, float& d2, float& d3,
                                         uint32_t a0, uint32_t a1, uint32_t a2, uint32_t a3,
                                         uint32_t b0, uint32_t b1) {
    asm volatile("mma.sync.aligned.m16n8k16.row.col.f32.bf16.bf16.f32 "
                 "{%0,%1,%2,%3}, {%4,%5,%6,%7}, {%8,%9}, {%0,%1,%2,%3};"
                 : "+f"(d0), "+f"(d1), "+f"(d2), "+f"(d3)
                 : "r"(a0), "r"(a1), "r"(a2), "r"(a3), "r"(b0), "r"(b1));
}

__device__ __forceinline__ void gemm_load_stage(uint32_t sb, int stage, int tid,
                                                const bf16* Ag, const bf16* Bg) {
    uint32_t abase = sb + stage * STAGE_BYTES;
    uint32_t bbase = abase + BM * APITCH * 2;
#pragma unroll
    for (int i = 0; i < 2; i++) {
        int idx = tid + 256 * i;
        int r = idx >> 2;
        int q = idx & 3;
        cp16(abase + r * (APITCH * 2) + q * 16, Ag + (size_t)r * Hh + q * 8);
        cp16(bbase + r * (APITCH * 2) + q * 16, Bg + (size_t)r * Hh + q * 8);
    }
}

struct GemmArgs {
    const bf16* A0; const bf16* A1;
    float* C0; float* C1;
    bf16* Cbf0; bf16* Cbf1;
    const float* PA0; const float* PB0;   // z=0: projection matrices [7][1024]
    const float* PA1;                     // z=1
    float* partA0; float* partB0;
    float* partA1;
    const bf16* Bt;
    const float* bias;
    int dotanh; int T;
};

__global__ void __launch_bounds__(256, 2)
mma_gemm(GemmArgs ga)
{
    extern __shared__ char smem[];
    uint32_t sb = smem_u32(smem);
    const int tid = threadIdx.x;
    const int wid = tid >> 5, lane = tid & 31;
    const int wm = wid >> 2, wn = wid & 3;
    const int n0 = blockIdx.x * BN;
    const size_t m0 = (size_t)blockIdx.y * BM;
    const int z = blockIdx.z;
    const bf16* A = z ? ga.A1 : ga.A0;
    float* C = z ? ga.C1 : ga.C0;
    bf16* Cbf = z ? ga.Cbf1 : ga.Cbf0;
    const float* PA = z ? ga.PA1 : ga.PA0;
    const float* PB = z ? nullptr : ga.PB0;
    float* partA = z ? ga.partA1 : ga.partA0;
    float* partB = z ? nullptr : ga.partB0;
    const int T = ga.T;

    float acc[4][4][4];
#pragma unroll
    for (int mi = 0; mi < 4; mi++)
#pragma unroll
        for (int ni = 0; ni < 4; ni++)
#pragma unroll
            for (int k = 0; k < 4; k++) acc[mi][ni][k] = 0.f;

    const bf16* Arow = A + m0 * Hh;
    const bf16* Brow = ga.Bt + (size_t)n0 * Hh;

    gemm_load_stage(sb, 0, tid, Arow, Brow);
    CP_COMMIT();
    gemm_load_stage(sb, 1, tid, Arow + BKg, Brow + BKg);
    CP_COMMIT();
    gemm_load_stage(sb, 2, tid, Arow + 2 * BKg, Brow + 2 * BKg);
    CP_COMMIT();

    const int tl = lane >> 3;
    const int l7 = lane & 7;

    for (int t = 0; t < T; t++) {
        CP_WAIT2();
        __syncthreads();
        int nc = t + 3;
        if (nc < T)
            gemm_load_stage(sb, nc % GSTG, tid, Arow + nc * BKg, Brow + nc * BKg);
        CP_COMMIT();

        uint32_t sA = sb + (t % GSTG) * STAGE_BYTES;
        uint32_t sB = sA + BM * APITCH * 2;
#pragma unroll
        for (int ks = 0; ks < 2; ks++) {
            uint32_t a[4][4];
#pragma unroll
            for (int mi = 0; mi < 4; mi++) {
                int row = wm * 64 + mi * 16 + (tl & 1) * 8 + l7;
                int col = ks * 16 + (tl >> 1) * 8;
                ldsm4(a[mi][0], a[mi][1], a[mi][2], a[mi][3],
                      sA + row * (APITCH * 2) + col * 2);
            }
            uint32_t bq[2][4];
#pragma unroll
            for (int nn = 0; nn < 2; nn++) {
                int row = wn * 32 + nn * 16 + (tl >> 1) * 8 + l7;
                int col = ks * 16 + (tl & 1) * 8;
                ldsm4(bq[nn][0], bq[nn][1], bq[nn][2], bq[nn][3],
                      sB + row * (APITCH * 2) + col * 2);
            }
#pragma unroll
            for (int mi = 0; mi < 4; mi++)
#pragma unroll
                for (int ni = 0; ni < 4; ni++)
                    mma_bf16(acc[mi][ni][0], acc[mi][ni][1], acc[mi][ni][2], acc[mi][ni][3],
                             a[mi][0], a[mi][1], a[mi][2], a[mi][3],
                             bq[ni >> 1][(ni & 1) * 2], bq[ni >> 1][(ni & 1) * 2 + 1]);
        }
    }
    __syncthreads();   // all compute done; smem reusable for epilogue

    const int lq = lane >> 2;
    const int lr = lane & 3;

    // transform acc in place (bias + tanh)
#pragma unroll
    for (int mi = 0; mi < 4; mi++)
#pragma unroll
        for (int ni = 0; ni < 4; ni++) {
            int col = n0 + wn * 32 + ni * 8 + lr * 2;
            float b0 = 0.f, b1 = 0.f;
            if (ga.bias) { b0 = ga.bias[col]; b1 = ga.bias[col + 1]; }
            acc[mi][ni][0] += b0; acc[mi][ni][1] += b1;
            acc[mi][ni][2] += b0; acc[mi][ni][3] += b1;
            if (ga.dotanh) {
#pragma unroll
                for (int k = 0; k < 4; k++) acc[mi][ni][k] = tanhf(acc[mi][ni][k]);
            }
        }

    // main writes
#pragma unroll
    for (int mi = 0; mi < 4; mi++) {
        int row = (int)m0 + wm * 64 + mi * 16 + lq;
#pragma unroll
        for (int ni = 0; ni < 4; ni++) {
            int col = n0 + wn * 32 + ni * 8 + lr * 2;
            if (C) {
                *(float2*)(C + (size_t)row * Hh + col) = make_float2(acc[mi][ni][0], acc[mi][ni][1]);
                *(float2*)(C + (size_t)(row + 8) * Hh + col) = make_float2(acc[mi][ni][2], acc[mi][ni][3]);
            }
            if (Cbf) {
                __nv_bfloat162 w0, w1;
                w0.x = __float2bfloat16_rn(acc[mi][ni][0]); w0.y = __float2bfloat16_rn(acc[mi][ni][1]);
                w1.x = __float2bfloat16_rn(acc[mi][ni][2]); w1.y = __float2bfloat16_rn(acc[mi][ni][3]);
                *(__nv_bfloat162*)(Cbf + (size_t)row * Hh + col) = w0;
                *(__nv_bfloat162*)(Cbf + (size_t)(row + 8) * Hh + col) = w1;
            }
        }
    }

    // split-K partial projections: part[ct][m0+rl][c] = sum_{col in tile} v * PU[c][n0+col]
    if (partA) {
        float* Us = (float*)smem;            // [2][128][7]
        float* red = Us + 2 * 128 * NCLS;    // [4][128]
        for (int idx = tid; idx < 128 * NCLS; idx += 256) {
            int col = idx / NCLS, c = idx % NCLS;
            Us[idx] = PA[c * Hh + n0 + col];
            if (PB) Us[128 * NCLS + idx] = PB[c * Hh + n0 + col];
        }
        __syncthreads();
        int nU = PB ? 2 : 1;
        for (int u = 0; u < nU; u++) {
            const float* U = Us + u * 128 * NCLS;
            float* part = (u == 0) ? partA : partB;
            for (int c = 0; c < NCLS; c++) {
                float tp[4][2];
#pragma unroll
                for (int mi = 0; mi < 4; mi++) { tp[mi][0] = 0.f; tp[mi][1] = 0.f; }
#pragma unroll
                for (int ni = 0; ni < 4; ni++) {
                    int coll = wn * 32 + ni * 8 + lr * 2;
                    float w0 = U[coll * NCLS + c];
                    float w1 = U[(coll + 1) * NCLS + c];
#pragma unroll
                    for (int mi = 0; mi < 4; mi++) {
                        tp[mi][0] += acc[mi][ni][0] * w0 + acc[mi][ni][1] * w1;
                        tp[mi][1] += acc[mi][ni][2] * w0 + acc[mi][ni][3] * w1;
                    }
                }
#pragma unroll
                for (int mi = 0; mi < 4; mi++)
#pragma unroll
                    for (int s = 0; s < 2; s++) {
                        float v = tp[mi][s];
                        v += __shfl_xor_sync(0xffffffffu, v, 1);
                        v += __shfl_xor_sync(0xffffffffu, v, 2);
                        tp[mi][s] = v;
                    }
                if (lr == 0) {
#pragma unroll
                    for (int mi = 0; mi < 4; mi++)
#pragma unroll
                        for (int s = 0; s < 2; s++)
                            red[wn * 128 + wm * 64 + mi * 16 + s * 8 + lq] = tp[mi][s];
                }
                __syncthreads();
                if (tid < 128) {
                    float v = red[tid] + red[128 + tid] + red[256 + tid] + red[384 + tid];
                    part[((size_t)blockIdx.x * ROWS + (m0 + tid)) * NCLS + c] = v;
                }
                __syncthreads();
            }
        }
    }
}

// =================== weight prep / converts ===================
__global__ void transpose_bf_kernel(const float* __restrict__ in, bf16* __restrict__ out,
                                    int K, int N)
{
    __shared__ float tile[32][33];
    int k0 = blockIdx.y * 32, n0 = blockIdx.x * 32;
    int tx = threadIdx.x, ty = threadIdx.y;
    for (int r = ty; r < 32; r += 8) tile[r][tx] = in[(size_t)(k0 + r) * N + n0 + tx];
    __syncthreads();
    for (int r = ty; r < 32; r += 8)
        out[(size_t)(n0 + r) * K + k0 + tx] = __float2bfloat16_rn(tile[tx][r]);
}
__global__ void repack_gatWt_kernel(const float* __restrict__ gw, bf16* __restrict__ Wgt)
{
    int idx = blockIdx.x * 256 + threadIdx.x;
    int n = idx >> 10, f = idx & 1023;
    int h = n >> 7, d = n & 127;
    Wgt[idx] = __float2bfloat16_rn(gw[((size_t)(h << 10 | f)) * NHID + d]);
}
__global__ void cvt_bf_kernel(const float* __restrict__ a, const float* __restrict__ b,
                              bf16* __restrict__ oa, bf16* __restrict__ ob)
{
    const float* src = blockIdx.y ? b : a;
    bf16* dst = blockIdx.y ? ob : oa;
    int idx = (blockIdx.x * 256 + threadIdx.x) * 4;
    float4 v = *(const float4*)(src + idx);
    __nv_bfloat162 w0, w1;
    w0.x = __float2bfloat16_rn(v.x); w0.y = __float2bfloat16_rn(v.y);
    w1.x = __float2bfloat16_rn(v.z); w1.y = __float2bfloat16_rn(v.w);
    *(__nv_bfloat162*)(dst + idx) = w0;
    *(__nv_bfloat162*)(dst + idx + 2) = w1;
}

__global__ void fold_u_kernel(const float* __restrict__ lin0W,
                              const float* __restrict__ clsW,
                              float* __restrict__ U0t, float* __restrict__ U1t)
{
    int r = blockIdx.x;
    int c = threadIdx.x >> 5, l = threadIdx.x & 31;
    const float* row = lin0W + (size_t)r * Hh;
    float acc = 0.f;
    for (int k = l; k < Hh; k += 32) acc += row[k] * clsW[k * NCLS + c];
    for (int o = 16; o > 0; o >>= 1) acc += __shfl_down_sync(0xffffffffu, acc, o);
    if (l == 0) {
        if (r < Hh) U0t[c * Hh + r] = acc;
        else        U1t[c * Hh + (r - Hh)] = acc;
    }
}
__global__ void fold_u2_kernel(const float* __restrict__ lin1W,
                               const float* __restrict__ U1t,
                               float* __restrict__ U2t)
{
    int r = blockIdx.x;
    int c = threadIdx.x >> 5, l = threadIdx.x & 31;
    const float* row = lin1W + (size_t)r * Hh;
    const float* u1 = U1t + c * Hh;
    float acc = 0.f;
    for (int k = l; k < Hh; k += 32) acc += row[k] * u1[k];
    for (int o = 16; o > 0; o >>= 1) acc += __shfl_down_sync(0xffffffffu, acc, o);
    if (l == 0) U2t[c * Hh + r] = acc;
}
__global__ void fold_cvec_kernel(const float* __restrict__ lin0b,
                                 const float* __restrict__ lin1b,
                                 const float* __restrict__ clsW,
                                 const float* __restrict__ clsb,
                                 const float* __restrict__ U1t,
                                 float* __restrict__ cvec)
{
    int c = threadIdx.x >> 5, l = threadIdx.x & 31;
    float acc = 0.f;
    for (int k = l; k < Hh; k += 32)
        acc += lin0b[k] * clsW[k * NCLS + c] + lin1b[k] * U1t[c * Hh + k];
    for (int o = 16; o > 0; o >>= 1) acc += __shfl_down_sync(0xffffffffu, acc, o);
    if (l == 0) cvec[c] = acc + clsb[c];
}
__global__ void build_uet_kernel(const float* __restrict__ clsW, float* __restrict__ Uet)
{
    int idx = blockIdx.x * 256 + threadIdx.x;
    if (idx < NCLS * Hh) {
        int c = idx / Hh, k = idx % Hh;
        Uet[idx] = clsW[k * NCLS + c];
    }
}

// =================== small kernels ===================
__global__ void gat_scores_kernel(const float* __restrict__ Wh,
                                  const float* __restrict__ a1,
                                  const float* __restrict__ a2,
                                  float* __restrict__ s1, float* __restrict__ s2)
{
    int n = blockIdx.x;
    int w = threadIdx.x >> 5, l = threadIdx.x & 31;
    const float* row = Wh + (size_t)n * Hh + w * NHID;
    float x1 = 0.f, x2 = 0.f;
#pragma unroll
    for (int t = 0; t < 4; t++) {
        float v = row[l + 32 * t];
        x1 += v * a1[w * NHID + l + 32 * t];
        x2 += v * a2[w * NHID + l + 32 * t];
    }
    for (int o = 16; o > 0; o >>= 1) {
        x1 += __shfl_down_sync(0xffffffffu, x1, o);
        x2 += __shfl_down_sync(0xffffffffu, x2, o);
    }
    if (l == 0) { s1[n * HEADS + w] = x1; s2[n * HEADS + w] = x2; }
}

__global__ void mean_rows_kernel(const float* __restrict__ X, float* __restrict__ out)
{
    int b = blockIdx.y;
    int c = blockIdx.x * 256 + threadIdx.x;
    const float* p = X + (size_t)b * Nn * Hh + c;
    float s = 0.f;
    for (int n = 0; n < Nn; n++) s += p[(size_t)n * Hh];
    out[b * Hh + c] = s * (1.0f / Nn);
}

__device__ __forceinline__ float eluf(float x) { return x > 0.f ? x : expf(x) - 1.0f; }

__global__ void att1_tile_kernel(const float* __restrict__ Wh,
                                 const float* __restrict__ s1,
                                 const float* __restrict__ s2,
                                 bf16* __restrict__ h1)
{
    __shared__ float sW[54][128];
    __shared__ float sw[32][24];
    int b = blockIdx.z, h = blockIdx.y, it = blockIdx.x;
    int i0 = it * 32;
    int jlo0 = i0 - 23; if (jlo0 < 0) jlo0 = 0;
    int nrows = (i0 + 30) - jlo0 + 1;
    int tid = threadIdx.x;
    const float* base = Wh + (size_t)b * Nn * Hh + h * NHID;
    for (int rr = 0; rr < nrows; rr++)
        sW[rr][tid] = base[(size_t)(jlo0 + rr) * Hh + tid];
    if (tid < 32) {
        int i = i0 + tid;
        if (i > 0) {
            int jl = i - 23; if (jl < 0) jl = 0;
            int L = i - jl;
            float si = s1[((size_t)b * Nn + i) * HEADS + h];
            float mx = -1e30f;
            for (int t = 0; t < L; t++) {
                float v = si + s2[((size_t)b * Nn + jl + t) * HEADS + h];
                v = v > 0.f ? v : ALPHA_LRELU * v;
                sw[tid][t] = v; mx = fmaxf(mx, v);
            }
            float ssum = 0.f;
            for (int t = 0; t < L; t++) { float ex = expf(sw[tid][t] - mx); sw[tid][t] = ex; ssum += ex; }
            float inv = 1.0f / ssum;
            for (int t = 0; t < L; t++) sw[tid][t] *= inv;
        }
    }
    __syncthreads();
    for (int il = 0; il < 32; il++) {
        int i = i0 + il;
        if (i == 0) continue;
        int jl = i - 23; if (jl < 0) jl = 0;
        int L = i - jl, roff = jl - jlo0;
        float acc = 0.f;
        for (int t = 0; t < L; t++) acc += sw[il][t] * sW[roff + t][tid];
        h1[((size_t)b * Nn + i) * Hh + h * NHID + tid] = __float2bfloat16_rn(eluf(acc));
    }
}

__global__ void att1_row0_kernel(const float* __restrict__ mean1, bf16* __restrict__ h1)
{
    int b = blockIdx.x;
    for (int c = threadIdx.x; c < Hh; c += 256)
        h1[(size_t)b * Nn * Hh + c] = __float2bfloat16_rn(eluf(mean1[b * Hh + c]));
}

__global__ void out_scores_kernel(const float* __restrict__ Wh2,
                                  const float* __restrict__ a1,
                                  const float* __restrict__ a2,
                                  float* __restrict__ s1, float* __restrict__ s2)
{
    int n = blockIdx.x;
    int tid = threadIdx.x;
    float x1 = 0.f, x2 = 0.f;
    const float* x = Wh2 + (size_t)n * Hh;
    for (int c = tid; c < Hh; c += 256) { float v = x[c]; x1 += v * a1[c]; x2 += v * a2[c]; }
    __shared__ float sh1[8], sh2[8];
    for (int o = 16; o > 0; o >>= 1) {
        x1 += __shfl_down_sync(0xffffffffu, x1, o);
        x2 += __shfl_down_sync(0xffffffffu, x2, o);
    }
    if ((tid & 31) == 0) { sh1[tid >> 5] = x1; sh2[tid >> 5] = x2; }
    __syncthreads();
    if (tid == 0) {
        float t1 = 0.f, t2 = 0.f;
        for (int k = 0; k < 8; k++) { t1 += sh1[k]; t2 += sh2[k]; }
        s1[n] = t1; s2[n] = t2;
    }
}

// band attention out layer: emits split-K partial projection onto U2t instead of h2
__global__ void att2_tile_kernel(const float* __restrict__ Wh2,
                                 const float* __restrict__ s1,
                                 const float* __restrict__ s2,
                                 const float* __restrict__ U2t,
                                 float* __restrict__ part)
{
    __shared__ float sW[54][128];
    __shared__ float sw[32][24];
    __shared__ float U2s[128 * NCLS];
    __shared__ float wr[4][NCLS];
    int b = blockIdx.z, ct = blockIdx.y, it = blockIdx.x;
    int i0 = it * 32, c0 = ct * 128;
    int jlo0 = i0 - 23; if (jlo0 < 0) jlo0 = 0;
    int nrows = (i0 + 30) - jlo0 + 1;
    int tid = threadIdx.x;
    int warp = tid >> 5, lane = tid & 31;
    const float* base = Wh2 + (size_t)b * Nn * Hh + c0;
    for (int rr = 0; rr < nrows; rr++)
        sW[rr][tid] = base[(size_t)(jlo0 + rr) * Hh + tid];
#pragma unroll
    for (int c = 0; c < NCLS; c++)
        U2s[tid * NCLS + c] = U2t[c * Hh + c0 + tid];
    if (tid < 32) {
        int i = i0 + tid;
        if (i > 0) {
            int jl = i - 23; if (jl < 0) jl = 0;
            int L = i - jl;
            float si = s1[(size_t)b * Nn + i];
            float mx = -1e30f;
            for (int t = 0; t < L; t++) {
                float v = si + s2[(size_t)b * Nn + jl + t];
                v = v > 0.f ? v : ALPHA_LRELU * v;
                sw[tid][t] = v; mx = fmaxf(mx, v);
            }
            float ssum = 0.f;
            for (int t = 0; t < L; t++) { float ex = expf(sw[tid][t] - mx); sw[tid][t] = ex; ssum += ex; }
            float inv = 1.0f / ssum;
            for (int t = 0; t < L; t++) sw[tid][t] *= inv;
        }
    }
    __syncthreads();
    for (int il = 0; il < 32; il++) {
        int i = i0 + il;
        if (i == 0) continue;
        int jl = i - 23; if (jl < 0) jl = 0;
        int L = i - jl, roff = jl - jlo0;
        float acc = 0.f;
        for (int t = 0; t < L; t++) acc += sw[il][t] * sW[roff + t][tid];
        float v = eluf(acc);
        float pr[NCLS];
#pragma unroll
        for (int c = 0; c < NCLS; c++) pr[c] = v * U2s[tid * NCLS + c];
        for (int o = 16; o > 0; o >>= 1)
#pragma unroll
            for (int c = 0; c < NCLS; c++) pr[c] += __shfl_down_sync(0xffffffffu, pr[c], o);
        if (lane == 0)
#pragma unroll
            for (int c = 0; c < NCLS; c++) wr[warp][c] = pr[c];
        __syncthreads();
        if (tid < NCLS) {
            float s = wr[0][tid] + wr[1][tid] + wr[2][tid] + wr[3][tid];
            part[((size_t)ct * ROWS + ((size_t)b * Nn + i)) * NCLS + tid] = s;
        }
        __syncthreads();
    }
}

// sum 8 column-tile partials (+ optional second source; row0 swaps source) + bias, softmax
__global__ void reduce_softmax_kernel(const float* __restrict__ base,
                                      const float* __restrict__ alt,
                                      const float* __restrict__ row0alt,
                                      const float* __restrict__ bias7,
                                      float* __restrict__ out)
{
    int tid = threadIdx.x;            // 224 = 32 n x 7 c
    int ni = tid / NCLS, c = tid % NCLS;
    int n = blockIdx.x * 32 + ni;
    int i = n & (Nn - 1);
    float s = bias7[c];
    const float* px = alt ? ((i == 0) ? row0alt : alt) : nullptr;
    for (int ct = 0; ct < NTILES; ct++) {
        size_t off = ((size_t)ct * ROWS + n) * NCLS + c;
        s += base[off];
        if (px) s += px[off];
    }
    __shared__ float sh[32][NCLS];
    sh[ni][c] = s;
    __syncthreads();
    if (c == 0) {
        float mx = sh[ni][0];
        for (int k = 1; k < NCLS; k++) mx = fmaxf(mx, sh[ni][k]);
        float e[NCLS], sum = 0.f;
        for (int k = 0; k < NCLS; k++) { e[k] = expf(sh[ni][k] - mx); sum += e[k]; }
        float inv = 1.0f / sum;
        for (int k = 0; k < NCLS; k++) out[n * NCLS + k] = e[k] * inv;
    }
}

__global__ void hmm_kernel(const float* __restrict__ Bprob,
                           const float* __restrict__ hmmA,
                           float* __restrict__ out)
{
    __shared__ float sAT[NCLS * NCLS];
    int tid = threadIdx.x;
    if (tid < NCLS * NCLS) sAT[tid] = hmmA[(tid % NCLS) * NCLS + (tid / NCLS)];
    __syncthreads();
    int gidx = blockIdx.x * 128 + tid;
    int b = gidx >> 8, i = gidx & 255;
    const float* Bp = Bprob + (size_t)b * Nn * NCLS;
    int t0 = i - (BAND - 1); if (t0 < 0) t0 = 0;
    float p[NCLS]; float s = 0.f;
#pragma unroll
    for (int r = 0; r < NCLS; r++) { p[r] = Bp[t0 * NCLS + r]; s += p[r]; }
    float inv = 1.0f / s;
#pragma unroll
    for (int r = 0; r < NCLS; r++) p[r] *= inv;
    for (int t = t0 + 1; t <= i; t++) {
        float q[NCLS]; s = 0.f;
#pragma unroll
        for (int r = 0; r < NCLS; r++) {
            float a = 0.f;
#pragma unroll
            for (int c = 0; c < NCLS; c++) a += sAT[r * NCLS + c] * p[c];
            a *= Bp[t * NCLS + r];
            q[r] = a; s += a;
        }
        inv = 1.0f / s;
#pragma unroll
        for (int r = 0; r < NCLS; r++) p[r] = q[r] * inv;
    }
#pragma unroll
    for (int r = 0; r < NCLS; r++) out[gidx * NCLS + r] = p[r];
}

__global__ void final_kernel(const float* __restrict__ log_gat,
                             const float* __restrict__ log_hmm,
                             const int* __restrict__ labels,
                             float* __restrict__ outLogits)
{
    int r = blockIdx.x * 256 + threadIdx.x;
    float lg[NCLS];
#pragma unroll
    for (int k = 0; k < NCLS; k++) {
        lg[k] = logf(0.5f * (log_gat[r * NCLS + k] + log_hmm[r * NCLS + k]));
        outLogits[r * NCLS + k] = lg[k];
    }
    int lab = labels[r];
    float picked = (lab >= 0) ? lg[lab] : 0.f;
    for (int o = 16; o > 0; o >>= 1) picked += __shfl_down_sync(0xffffffffu, picked, o);
    __shared__ float sh[8];
    if ((threadIdx.x & 31) == 0) sh[threadIdx.x >> 5] = picked;
    __syncthreads();
    if (threadIdx.x == 0) {
        float s = 0.f;
        for (int k = 0; k < 8; k++) s += sh[k];
        g_blocksums[blockIdx.x] = s;
    }
}

__global__ void finalize_kernel(float* d_out, int has_loss)
{
    if (has_loss) {
        float s = 0.f;
        for (int k = 0; k < 32; k++) s += g_blocksums[k];
        d_out[0] = -s / (float)ROWS;
    }
}

// ---------------- host launch ----------------
template <typename T>
static T* sym(const void* symbol)
{
    void* p = nullptr;
    cudaGetSymbolAddress(&p, symbol);
    return (T*)p;
}

extern "C" void kernel_launch(void* const* d_in, const int* in_sizes, int n_in,
                              void* d_out, int out_size)
{
    (void)in_sizes; (void)n_in;
    const float* hidden_cls = (const float*)d_in[0];
    const float* hidden_emo = (const float*)d_in[1];
    const int*   labels     = (const int*)d_in[3];
    const float* pooler_W   = (const float*)d_in[4];
    const float* pooler_b   = (const float*)d_in[5];
    const float* gat_W      = (const float*)d_in[6];
    const float* gat_a1     = (const float*)d_in[7];
    const float* gat_a2     = (const float*)d_in[8];
    const float* out_W      = (const float*)d_in[9];
    const float* out_a1     = (const float*)d_in[10];
    const float* out_a2     = (const float*)d_in[11];
    const float* lin1_W     = (const float*)d_in[12];
    const float* lin1_b     = (const float*)d_in[13];
    const float* lin0_W     = (const float*)d_in[14];
    const float* lin0_b     = (const float*)d_in[15];
    const float* cls_W      = (const float*)d_in[16];
    const float* cls_b      = (const float*)d_in[17];
    const float* hmm_A      = (const float*)d_in[18];

    float* Wh      = sym<float>(g_Wh);
    float* Wh2     = sym<float>(g_Wh2);
    float* s1      = sym<float>(g_s1);
    float* s2      = sym<float>(g_s2);
    float* s1b     = sym<float>(g_s1b);
    float* s2b     = sym<float>(g_s2b);
    float* mean1   = sym<float>(g_mean1);
    float* loggat  = sym<float>(g_loggat);
    float* Bprob   = sym<float>(g_Bprob);
    float* loghmm  = sym<float>(g_loghmm);
    bf16* hidcbf   = sym<bf16>(g_hid_cls_bf);
    bf16* hidebf   = sym<bf16>(g_hid_emo_bf);
    bf16* feacbf   = sym<bf16>(g_fea_cls_bf);
    bf16* h1bf     = sym<bf16>(g_h1_bf);
    bf16* poolWt   = sym<bf16>(g_poolWt);
    bf16* Wgt      = sym<bf16>(g_Wgt);
    bf16* outWt    = sym<bf16>(g_outWt);
    float* U0t     = sym<float>(g_U0t);
    float* U1t     = sym<float>(g_U1t);
    float* U2t     = sym<float>(g_U2t);
    float* Uet     = sym<float>(g_Uet);
    float* cvec    = sym<float>(g_cvec);
    float* part_u0  = sym<float>(g_part_u0);
    float* part_u2f = sym<float>(g_part_u2f);
    float* part_cls = sym<float>(g_part_cls);
    float* part_att2 = sym<float>(g_part_att2);

    cudaFuncSetAttribute(mma_gemm, cudaFuncAttributeMaxDynamicSharedMemorySize, GEMM_SMEM);

    int has_loss = (out_size == ROWS * NCLS + 1) ? 1 : 0;
    float* outLogits = has_loss ? ((float*)d_out + 1) : (float*)d_out;

    // 0) weight prep + input converts + classifier folding
    {
        dim3 blk(32, 8);
        transpose_bf_kernel<<<dim3(Hh / 32, Hh / 32), blk>>>(pooler_W, poolWt, Hh, Hh);
        transpose_bf_kernel<<<dim3(Hh / 32, Hh / 32), blk>>>(out_W, outWt, Hh, Hh);
        repack_gatWt_kernel<<<(Hh * Hh) / 256, 256>>>(gat_W, Wgt);
        cvt_bf_kernel<<<dim3(ROWS * Hh / 1024, 2), 256>>>(hidden_cls, hidden_emo, hidcbf, hidebf);
        fold_u_kernel<<<2 * Hh, 224>>>(lin0_W, cls_W, U0t, U1t);
        fold_u2_kernel<<<Hh, 224>>>(lin1_W, U1t, U2t);
        fold_cvec_kernel<<<1, 224>>>(lin0_b, lin1_b, cls_W, cls_b, U1t, cvec);
        build_uet_kernel<<<(NCLS * Hh + 255) / 256, 256>>>(cls_W, Uet);
    }

    // 1) poolers, z-batched. z0: bf16 fea_cls + U0/U2 partials; z1: cls partials only.
    {
        GemmArgs ga = {};
        ga.A0 = hidcbf; ga.A1 = hidebf;
        ga.C0 = nullptr; ga.C1 = nullptr;
        ga.Cbf0 = feacbf; ga.Cbf1 = nullptr;
        ga.PA0 = U0t; ga.PB0 = U2t; ga.PA1 = Uet;
        ga.partA0 = part_u0; ga.partB0 = part_u2f; ga.partA1 = part_cls;
        ga.Bt = poolWt; ga.bias = pooler_b; ga.dotanh = 1; ga.T = Hh / BKg;
        mma_gemm<<<dim3(Hh / BN, ROWS / BM, 2), 256, GEMM_SMEM>>>(ga);
    }

    // 2) GAT layer 1
    {
        GemmArgs ga = {};
        ga.A0 = feacbf; ga.C0 = Wh;
        ga.Bt = Wgt; ga.dotanh = 0; ga.T = Hh / BKg;
        mma_gemm<<<dim3(Hh / BN, ROWS / BM, 1), 256, GEMM_SMEM>>>(ga);
    }
    gat_scores_kernel<<<ROWS, 256>>>(Wh, gat_a1, gat_a2, s1, s2);
    mean_rows_kernel<<<dim3(Hh / 256, Bc), 256>>>(Wh, mean1);
    att1_tile_kernel<<<dim3(8, 8, Bc), 128>>>(Wh, s1, s2, h1bf);
    att1_row0_kernel<<<Bc, 256>>>(mean1, h1bf);

    // 3) GAT out layer
    {
        GemmArgs ga = {};
        ga.A0 = h1bf; ga.C0 = Wh2;
        ga.Bt = outWt; ga.dotanh = 0; ga.T = Hh / BKg;
        mma_gemm<<<dim3(Hh / BN, ROWS / BM, 1), 256, GEMM_SMEM>>>(ga);
    }
    out_scores_kernel<<<ROWS, 256>>>(Wh2, out_a1, out_a2, s1b, s2b);
    att2_tile_kernel<<<dim3(8, 8, Bc), 128>>>(Wh2, s1b, s2b, U2t, part_att2);

    // 4) reduce partials -> GAT probs and HMM emission probs
    reduce_softmax_kernel<<<ROWS / 32, 224>>>(part_u0, part_att2, part_u2f, cvec, loggat);
    reduce_softmax_kernel<<<ROWS / 32, 224>>>(part_cls, nullptr, nullptr, cls_b, Bprob);

    // 5) HMM band filter
    hmm_kernel<<<ROWS / 128, 128>>>(Bprob, hmm_A, loghmm);

    // 6) final logits + loss
    final_kernel<<<ROWS / 256, 256>>>(loggat, loghmm, labels, outLogits);
    finalize_kernel<<<1, 1>>>((float*)d_out, has_loss);
}

// round 9
// speedup vs baseline: 1.5447x; 1.5447x over previous
#include <cuda_runtime.h>
#include <cuda_bf16.h>
#include <math.h>
#include <stdint.h>

// Problem constants
#define Bc   32
#define Nn   256
#define Hh   1024
#define HEADS 8
#define NHID 128
#define NCLS 7
#define BAND 24
#define ROWS (Bc*Nn)          // 8192
#define ALPHA_LRELU 0.2f

typedef __nv_bfloat16 bf16;

// ---------------- device scratch (no allocs allowed) ----------------
__device__ float g_fea_cls[ROWS*Hh];
__device__ float g_fea_emo[ROWS*Hh];
__device__ float g_Wh[ROWS*Hh];
__device__ float g_Wh2[ROWS*Hh];
__device__ float g_h2[ROWS*Hh];
__device__ float g_s1b[ROWS];
__device__ float g_s2b[ROWS];
__device__ float g_mean1[Bc*Hh];
__device__ float g_loggat[ROWS*NCLS];
__device__ float g_Bprob[ROWS*NCLS];
__device__ float g_loghmm[ROWS*NCLS];
__device__ float g_blocksums[32];
// bf16 operands
__device__ bf16 g_hid_cls_bf[ROWS*Hh];
__device__ bf16 g_hid_emo_bf[ROWS*Hh];
__device__ bf16 g_fea_cls_bf[ROWS*Hh];
__device__ bf16 g_h1_bf[ROWS*Hh];
__device__ bf16 g_poolWt[Hh*Hh];   // [N][K] k-major
__device__ bf16 g_Wgt[Hh*Hh];
__device__ bf16 g_outWt[Hh*Hh];
// folded classifier tables
__device__ float g_U0t[NCLS*Hh];
__device__ float g_U1t[NCLS*Hh];
__device__ float g_U2t[NCLS*Hh];
__device__ float g_cvec[NCLS];

// =================== bf16 mma.sync GEMM (4-stage cp.async pipeline) ==========
#define BM 128
#define BN 128
#define BKg 32
#define GSTG 4
#define APITCH 40                             // halves per smem row (80 B)
#define STAGE_BYTES (2 * BM * APITCH * 2)     // A + B = 20480 B
#define GEMM_SMEM (GSTG * STAGE_BYTES)        // 81920 B

__device__ __forceinline__ uint32_t smem_u32(const void* p) {
    uint32_t a;
    asm("{ .reg .u64 t; cvta.to.shared.u64 t, %1; cvt.u32.u64 %0, t; }" : "=r"(a) : "l"(p));
    return a;
}
__device__ __forceinline__ void cp16(uint32_t s, const void* g) {
    asm volatile("cp.async.cg.shared.global [%0], [%1], 16;" :: "r"(s), "l"(g));
}
#define CP_COMMIT() asm volatile("cp.async.commit_group;" ::: "memory")
#define CP_WAIT2()  asm volatile("cp.async.wait_group 2;" ::: "memory")

__device__ __forceinline__ void ldsm4(uint32_t& r0, uint32_t& r1, uint32_t& r2, uint32_t& r3,
                                      uint32_t addr) {
    asm volatile("ldmatrix.sync.aligned.m8n8.x4.shared.b16 {%0,%1,%2,%3}, [%4];"
                 : "=r"(r0), "=r"(r1), "=r"(r2), "=r"(r3) : "r"(addr));
}
__device__ __forceinline__ void mma_bf16(float& d0, float& d1, float& d2, float& d3,
                                         uint32_t a0, uint32_t a1, uint32_t a2, uint32_t a3,
                                         uint32_t b0, uint32_t b1) {
    asm volatile("mma.sync.aligned.m16n8k16.row.col.f32.bf16.bf16.f32 "
                 "{%0,%1,%2,%3}, {%4,%5,%6,%7}, {%8,%9}, {%0,%1,%2,%3};"
                 : "+f"(d0), "+f"(d1), "+f"(d2), "+f"(d3)
                 : "r"(a0), "r"(a1), "r"(a2), "r"(a3), "r"(b0), "r"(b1));
}

__device__ __forceinline__ void gemm_load_stage(uint32_t sb, int stage, int tid,
                                                const bf16* Ag, const bf16* Bg) {
    uint32_t abase = sb + stage * STAGE_BYTES;
    uint32_t bbase = abase + BM * APITCH * 2;
#pragma unroll
    for (int i = 0; i < 2; i++) {
        int idx = tid + 256 * i;
        int r = idx >> 2;
        int q = idx & 3;
        cp16(abase + r * (APITCH * 2) + q * 16, Ag + (size_t)r * Hh + q * 8);
        cp16(bbase + r * (APITCH * 2) + q * 16, Bg + (size_t)r * Hh + q * 8);
    }
}

// z-batched: blockIdx.z selects (Aa,Ca,Cbfa) or (Ab,Cb,Cbfb). B shared.
__global__ void __launch_bounds__(256, 2)
mma_gemm(const bf16* __restrict__ Aa, const bf16* __restrict__ Ab,
         float* __restrict__ Ca, float* __restrict__ Cb,
         bf16* __restrict__ Cbfa, bf16* __restrict__ Cbfb,
         const bf16* __restrict__ Bt,
         const float* __restrict__ bias, int dotanh, int T)
{
    extern __shared__ char smem[];
    uint32_t sb = smem_u32(smem);
    const int tid = threadIdx.x;
    const int wid = tid >> 5, lane = tid & 31;
    const int wm = wid >> 2, wn = wid & 3;   // 2x4 warp grid, warp tile 64x32
    const int n0 = blockIdx.x * BN;
    const size_t m0 = (size_t)blockIdx.y * BM;
    const bf16* A = (blockIdx.z == 0) ? Aa : Ab;
    float* C = (blockIdx.z == 0) ? Ca : Cb;
    bf16* Cbf = (blockIdx.z == 0) ? Cbfa : Cbfb;

    float acc[4][4][4];
#pragma unroll
    for (int mi = 0; mi < 4; mi++)
#pragma unroll
        for (int ni = 0; ni < 4; ni++)
#pragma unroll
            for (int k = 0; k < 4; k++) acc[mi][ni][k] = 0.f;

    const bf16* Arow = A + m0 * Hh;
    const bf16* Brow = Bt + (size_t)n0 * Hh;

    gemm_load_stage(sb, 0, tid, Arow, Brow);
    CP_COMMIT();
    gemm_load_stage(sb, 1, tid, Arow + BKg, Brow + BKg);
    CP_COMMIT();
    gemm_load_stage(sb, 2, tid, Arow + 2 * BKg, Brow + 2 * BKg);
    CP_COMMIT();

    const int tl = lane >> 3;          // ldmatrix tile selector
    const int l7 = lane & 7;

    for (int t = 0; t < T; t++) {
        CP_WAIT2();
        __syncthreads();
        int nc = t + 3;
        if (nc < T)
            gemm_load_stage(sb, nc % GSTG, tid, Arow + nc * BKg, Brow + nc * BKg);
        CP_COMMIT();   // always commit to keep group counting sound

        uint32_t sA = sb + (t % GSTG) * STAGE_BYTES;
        uint32_t sB = sA + BM * APITCH * 2;
#pragma unroll
        for (int ks = 0; ks < 2; ks++) {
            uint32_t a[4][4];
#pragma unroll
            for (int mi = 0; mi < 4; mi++) {
                int row = wm * 64 + mi * 16 + (tl & 1) * 8 + l7;
                int col = ks * 16 + (tl >> 1) * 8;
                ldsm4(a[mi][0], a[mi][1], a[mi][2], a[mi][3],
                      sA + row * (APITCH * 2) + col * 2);
            }
            uint32_t bq[2][4];
#pragma unroll
            for (int nn = 0; nn < 2; nn++) {
                int row = wn * 32 + nn * 16 + (tl >> 1) * 8 + l7;
                int col = ks * 16 + (tl & 1) * 8;
                ldsm4(bq[nn][0], bq[nn][1], bq[nn][2], bq[nn][3],
                      sB + row * (APITCH * 2) + col * 2);
            }
#pragma unroll
            for (int mi = 0; mi < 4; mi++)
#pragma unroll
                for (int ni = 0; ni < 4; ni++)
                    mma_bf16(acc[mi][ni][0], acc[mi][ni][1], acc[mi][ni][2], acc[mi][ni][3],
                             a[mi][0], a[mi][1], a[mi][2], a[mi][3],
                             bq[ni >> 1][(ni & 1) * 2], bq[ni >> 1][(ni & 1) * 2 + 1]);
        }
    }

    const int lq = lane >> 2;
    const int lr = lane & 3;
#pragma unroll
    for (int mi = 0; mi < 4; mi++) {
        int row = (int)m0 + wm * 64 + mi * 16 + lq;
#pragma unroll
        for (int ni = 0; ni < 4; ni++) {
            int col = n0 + wn * 32 + ni * 8 + lr * 2;
            float b0 = 0.f, b1 = 0.f;
            if (bias) { b0 = bias[col]; b1 = bias[col + 1]; }
            float2 v0, v1;
            v0.x = acc[mi][ni][0] + b0; v0.y = acc[mi][ni][1] + b1;
            v1.x = acc[mi][ni][2] + b0; v1.y = acc[mi][ni][3] + b1;
            if (dotanh) {
                v0.x = tanhf(v0.x); v0.y = tanhf(v0.y);
                v1.x = tanhf(v1.x); v1.y = tanhf(v1.y);
            }
            if (C) {
                *(float2*)(C + (size_t)row * Hh + col) = v0;
                *(float2*)(C + (size_t)(row + 8) * Hh + col) = v1;
            }
            if (Cbf) {
                __nv_bfloat162 w0, w1;
                w0.x = __float2bfloat16_rn(v0.x); w0.y = __float2bfloat16_rn(v0.y);
                w1.x = __float2bfloat16_rn(v1.x); w1.y = __float2bfloat16_rn(v1.y);
                *(__nv_bfloat162*)(Cbf + (size_t)row * Hh + col) = w0;
                *(__nv_bfloat162*)(Cbf + (size_t)(row + 8) * Hh + col) = w1;
            }
        }
    }
}

// =================== weight prep / converts ===================
__global__ void transpose_bf_kernel(const float* __restrict__ in, bf16* __restrict__ out,
                                    int K, int N)
{
    __shared__ float tile[32][33];
    int k0 = blockIdx.y * 32, n0 = blockIdx.x * 32;
    int tx = threadIdx.x, ty = threadIdx.y;
    for (int r = ty; r < 32; r += 8) tile[r][tx] = in[(size_t)(k0 + r) * N + n0 + tx];
    __syncthreads();
    for (int r = ty; r < 32; r += 8)
        out[(size_t)(n0 + r) * K + k0 + tx] = __float2bfloat16_rn(tile[tx][r]);
}
__global__ void repack_gatWt_kernel(const float* __restrict__ gw, bf16* __restrict__ Wgt)
{
    int idx = blockIdx.x * 256 + threadIdx.x;
    int n = idx >> 10, f = idx & 1023;
    int h = n >> 7, d = n & 127;
    Wgt[idx] = __float2bfloat16_rn(gw[((size_t)(h << 10 | f)) * NHID + d]);
}
__global__ void cvt_bf_kernel(const float* __restrict__ a, const float* __restrict__ b,
                              bf16* __restrict__ oa, bf16* __restrict__ ob)
{
    const float* src = blockIdx.y ? b : a;
    bf16* dst = blockIdx.y ? ob : oa;
    int idx = (blockIdx.x * 256 + threadIdx.x) * 4;
    float4 v = *(const float4*)(src + idx);
    __nv_bfloat162 w0, w1;
    w0.x = __float2bfloat16_rn(v.x); w0.y = __float2bfloat16_rn(v.y);
    w1.x = __float2bfloat16_rn(v.z); w1.y = __float2bfloat16_rn(v.w);
    *(__nv_bfloat162*)(dst + idx) = w0;
    *(__nv_bfloat162*)(dst + idx + 2) = w1;
}

__global__ void fold_u_kernel(const float* __restrict__ lin0W,
                              const float* __restrict__ clsW,
                              float* __restrict__ U0t, float* __restrict__ U1t)
{
    int r = blockIdx.x;
    int c = threadIdx.x >> 5, l = threadIdx.x & 31;
    const float* row = lin0W + (size_t)r * Hh;
    float acc = 0.f;
    for (int k = l; k < Hh; k += 32) acc += row[k] * clsW[k * NCLS + c];
    for (int o = 16; o > 0; o >>= 1) acc += __shfl_down_sync(0xffffffffu, acc, o);
    if (l == 0) {
        if (r < Hh) U0t[c * Hh + r] = acc;
        else        U1t[c * Hh + (r - Hh)] = acc;
    }
}
__global__ void fold_u2_kernel(const float* __restrict__ lin1W,
                               const float* __restrict__ U1t,
                               float* __restrict__ U2t)
{
    int r = blockIdx.x;
    int c = threadIdx.x >> 5, l = threadIdx.x & 31;
    const float* row = lin1W + (size_t)r * Hh;
    const float* u1 = U1t + c * Hh;
    float acc = 0.f;
    for (int k = l; k < Hh; k += 32) acc += row[k] * u1[k];
    for (int o = 16; o > 0; o >>= 1) acc += __shfl_down_sync(0xffffffffu, acc, o);
    if (l == 0) U2t[c * Hh + r] = acc;
}
__global__ void fold_cvec_kernel(const float* __restrict__ lin0b,
                                 const float* __restrict__ lin1b,
                                 const float* __restrict__ clsW,
                                 const float* __restrict__ clsb,
                                 const float* __restrict__ U1t,
                                 float* __restrict__ cvec)
{
    int c = threadIdx.x >> 5, l = threadIdx.x & 31;
    float acc = 0.f;
    for (int k = l; k < Hh; k += 32)
        acc += lin0b[k] * clsW[k * NCLS + c] + lin1b[k] * U1t[c * Hh + k];
    for (int o = 16; o > 0; o >>= 1) acc += __shfl_down_sync(0xffffffffu, acc, o);
    if (l == 0) cvec[c] = acc + clsb[c];
}

// =================== small kernels ===================
__global__ void mean_rows_kernel(const float* __restrict__ X, float* __restrict__ out)
{
    int b = blockIdx.y;
    int c = blockIdx.x * 256 + threadIdx.x;
    const float* p = X + (size_t)b * Nn * Hh + c;
    float s = 0.f;
    for (int n = 0; n < Nn; n++) s += p[(size_t)n * Hh];
    out[b * Hh + c] = s * (1.0f / Nn);
}

__device__ __forceinline__ float eluf(float x) { return x > 0.f ? x : expf(x) - 1.0f; }

// band attention layer 1 (per-head) with fused score computation.
// grid(8 i-tiles, 8 heads, 32 batches), 128 threads.
__global__ void att1_tile_kernel(const float* __restrict__ Wh,
                                 const float* __restrict__ gat_a1,
                                 const float* __restrict__ gat_a2,
                                 bf16* __restrict__ h1)
{
    __shared__ float sW[55][128];
    __shared__ float sc1[55], sc2[55];
    __shared__ float sw[32][24];
    int b = blockIdx.z, h = blockIdx.y, it = blockIdx.x;
    int i0 = it * 32;
    int jlo0 = i0 - 23; if (jlo0 < 0) jlo0 = 0;
    int nrows = (i0 + 31) - jlo0 + 1;          // includes all query rows; <= 55
    int tid = threadIdx.x;
    int warp = tid >> 5, lane = tid & 31;
    const float* base = Wh + (size_t)b * Nn * Hh + h * NHID;
    for (int rr = 0; rr < nrows; rr++)
        sW[rr][tid] = base[(size_t)(jlo0 + rr) * Hh + tid];
    __syncthreads();
    // fused scores: warp w handles rows rr = w, w+4, ... (same reduce order as before)
    {
        float a1v[4], a2v[4];
#pragma unroll
        for (int t = 0; t < 4; t++) {
            a1v[t] = gat_a1[h * NHID + lane + 32 * t];
            a2v[t] = gat_a2[h * NHID + lane + 32 * t];
        }
        for (int rr = warp; rr < nrows; rr += 4) {
            float d1 = 0.f, d2 = 0.f;
#pragma unroll
            for (int t = 0; t < 4; t++) {
                float v = sW[rr][lane + 32 * t];
                d1 += v * a1v[t];
                d2 += v * a2v[t];
            }
            for (int o = 16; o > 0; o >>= 1) {
                d1 += __shfl_down_sync(0xffffffffu, d1, o);
                d2 += __shfl_down_sync(0xffffffffu, d2, o);
            }
            if (lane == 0) { sc1[rr] = d1; sc2[rr] = d2; }
        }
    }
    __syncthreads();
    if (tid < 32) {
        int i = i0 + tid;
        if (i > 0) {
            int jl = i - 23; if (jl < 0) jl = 0;
            int L = i - jl;
            float si = sc1[i - jlo0];
            float mx = -1e30f;
            for (int t = 0; t < L; t++) {
                float v = si + sc2[jl + t - jlo0];
                v = v > 0.f ? v : ALPHA_LRELU * v;
                sw[tid][t] = v; mx = fmaxf(mx, v);
            }
            float ssum = 0.f;
            for (int t = 0; t < L; t++) { float ex = expf(sw[tid][t] - mx); sw[tid][t] = ex; ssum += ex; }
            float inv = 1.0f / ssum;
            for (int t = 0; t < L; t++) sw[tid][t] *= inv;
        }
    }
    __syncthreads();
    for (int il = 0; il < 32; il++) {
        int i = i0 + il;
        if (i == 0) continue;
        int jl = i - 23; if (jl < 0) jl = 0;
        int L = i - jl, roff = jl - jlo0;
        float acc = 0.f;
        for (int t = 0; t < L; t++) acc += sw[il][t] * sW[roff + t][tid];
        h1[((size_t)b * Nn + i) * Hh + h * NHID + tid] = __float2bfloat16_rn(eluf(acc));
    }
}

__global__ void att1_row0_kernel(const float* __restrict__ mean1, bf16* __restrict__ h1)
{
    int b = blockIdx.x;
    for (int c = threadIdx.x; c < Hh; c += 256)
        h1[(size_t)b * Nn * Hh + c] = __float2bfloat16_rn(eluf(mean1[b * Hh + c]));
}

__global__ void out_scores_kernel(const float* __restrict__ Wh2,
                                  const float* __restrict__ a1,
                                  const float* __restrict__ a2,
                                  float* __restrict__ s1, float* __restrict__ s2)
{
    int n = blockIdx.x;
    int tid = threadIdx.x;
    float x1 = 0.f, x2 = 0.f;
    const float* x = Wh2 + (size_t)n * Hh;
    for (int c = tid; c < Hh; c += 256) { float v = x[c]; x1 += v * a1[c]; x2 += v * a2[c]; }
    __shared__ float sh1[8], sh2[8];
    for (int o = 16; o > 0; o >>= 1) {
        x1 += __shfl_down_sync(0xffffffffu, x1, o);
        x2 += __shfl_down_sync(0xffffffffu, x2, o);
    }
    if ((tid & 31) == 0) { sh1[tid >> 5] = x1; sh2[tid >> 5] = x2; }
    __syncthreads();
    if (tid == 0) {
        float t1 = 0.f, t2 = 0.f;
        for (int k = 0; k < 8; k++) { t1 += sh1[k]; t2 += sh2[k]; }
        s1[n] = t1; s2[n] = t2;
    }
}

__global__ void att2_tile_kernel(const float* __restrict__ Wh2,
                                 const float* __restrict__ s1,
                                 const float* __restrict__ s2,
                                 float* __restrict__ out)
{
    __shared__ float sW[54][128];
    __shared__ float sw[32][24];
    int b = blockIdx.z, ct = blockIdx.y, it = blockIdx.x;
    int i0 = it * 32, c0 = ct * 128;
    int jlo0 = i0 - 23; if (jlo0 < 0) jlo0 = 0;
    int nrows = (i0 + 30) - jlo0 + 1;
    int tid = threadIdx.x;
    const float* base = Wh2 + (size_t)b * Nn * Hh + c0;
    for (int rr = 0; rr < nrows; rr++)
        sW[rr][tid] = base[(size_t)(jlo0 + rr) * Hh + tid];
    if (tid < 32) {
        int i = i0 + tid;
        if (i > 0) {
            int jl = i - 23; if (jl < 0) jl = 0;
            int L = i - jl;
            float si = s1[(size_t)b * Nn + i];
            float mx = -1e30f;
            for (int t = 0; t < L; t++) {
                float v = si + s2[(size_t)b * Nn + jl + t];
                v = v > 0.f ? v : ALPHA_LRELU * v;
                sw[tid][t] = v; mx = fmaxf(mx, v);
            }
            float ssum = 0.f;
            for (int t = 0; t < L; t++) { float ex = expf(sw[tid][t] - mx); sw[tid][t] = ex; ssum += ex; }
            float inv = 1.0f / ssum;
            for (int t = 0; t < L; t++) sw[tid][t] *= inv;
        }
    }
    __syncthreads();
    for (int il = 0; il < 32; il++) {
        int i = i0 + il;
        if (i == 0) continue;
        int jl = i - 23; if (jl < 0) jl = 0;
        int L = i - jl, roff = jl - jlo0;
        float acc = 0.f;
        for (int t = 0; t < L; t++) acc += sw[il][t] * sW[roff + t][tid];
        out[((size_t)b * Nn + i) * Hh + c0 + tid] = eluf(acc);
    }
}

__global__ void gat_logits_kernel(const float* __restrict__ fea_cls,
                                  const float* __restrict__ h2,
                                  const float* __restrict__ U0t,
                                  const float* __restrict__ U2t,
                                  const float* __restrict__ cvec,
                                  float* __restrict__ out)
{
    int n = blockIdx.x;
    int i = n & (Nn - 1);
    int c = threadIdx.x >> 5, l = threadIdx.x & 31;
    const float* frow = fea_cls + (size_t)n * Hh;
    const float* hrow = (i == 0) ? frow : h2 + (size_t)n * Hh;
    const float* u0 = U0t + c * Hh;
    const float* u2 = U2t + c * Hh;
    float acc = 0.f;
    for (int k = l; k < Hh; k += 32)
        acc += frow[k] * u0[k] + hrow[k] * u2[k];
    for (int o = 16; o > 0; o >>= 1) acc += __shfl_down_sync(0xffffffffu, acc, o);
    __shared__ float sh[NCLS];
    if (l == 0) sh[c] = acc + cvec[c];
    __syncthreads();
    if (threadIdx.x == 0) {
        float mx = sh[0];
        for (int k = 1; k < NCLS; k++) mx = fmaxf(mx, sh[k]);
        float e[NCLS], s = 0.f;
        for (int k = 0; k < NCLS; k++) { e[k] = expf(sh[k] - mx); s += e[k]; }
        float inv = 1.0f / s;
        for (int k = 0; k < NCLS; k++) out[n * NCLS + k] = e[k] * inv;
    }
}

__global__ void cls_softmax_kernel(const float* __restrict__ X,
                                   const float* __restrict__ W,
                                   const float* __restrict__ bcls,
                                   float* __restrict__ out)
{
    int n = blockIdx.x;
    int wid = threadIdx.x >> 5, l = threadIdx.x & 31;
    __shared__ float sh[NCLS];
    const float* x = X + (size_t)n * Hh;
    float acc = 0.f;
    for (int t = l; t < Hh; t += 32) acc += x[t] * W[t * NCLS + wid];
    for (int o = 16; o > 0; o >>= 1) acc += __shfl_down_sync(0xffffffffu, acc, o);
    if (l == 0) sh[wid] = acc + bcls[wid];
    __syncthreads();
    if (threadIdx.x == 0) {
        float mx = sh[0];
        for (int k = 1; k < NCLS; k++) mx = fmaxf(mx, sh[k]);
        float e[NCLS], s = 0.f;
        for (int k = 0; k < NCLS; k++) { e[k] = expf(sh[k] - mx); s += e[k]; }
        float inv = 1.0f / s;
        for (int k = 0; k < NCLS; k++) out[n * NCLS + k] = e[k] * inv;
    }
}

__global__ void hmm_kernel(const float* __restrict__ Bprob,
                           const float* __restrict__ hmmA,
                           float* __restrict__ out)
{
    __shared__ float sAT[NCLS * NCLS];
    int tid = threadIdx.x;
    if (tid < NCLS * NCLS) sAT[tid] = hmmA[(tid % NCLS) * NCLS + (tid / NCLS)];
    __syncthreads();
    int gidx = blockIdx.x * 128 + tid;
    int b = gidx >> 8, i = gidx & 255;
    const float* Bp = Bprob + (size_t)b * Nn * NCLS;
    int t0 = i - (BAND - 1); if (t0 < 0) t0 = 0;
    float p[NCLS]; float s = 0.f;
#pragma unroll
    for (int r = 0; r < NCLS; r++) { p[r] = Bp[t0 * NCLS + r]; s += p[r]; }
    float inv = 1.0f / s;
#pragma unroll
    for (int r = 0; r < NCLS; r++) p[r] *= inv;
    for (int t = t0 + 1; t <= i; t++) {
        float q[NCLS]; s = 0.f;
#pragma unroll
        for (int r = 0; r < NCLS; r++) {
            float a = 0.f;
#pragma unroll
            for (int c = 0; c < NCLS; c++) a += sAT[r * NCLS + c] * p[c];
            a *= Bp[t * NCLS + r];
            q[r] = a; s += a;
        }
        inv = 1.0f / s;
#pragma unroll
        for (int r = 0; r < NCLS; r++) p[r] = q[r] * inv;
    }
#pragma unroll
    for (int r = 0; r < NCLS; r++) out[gidx * NCLS + r] = p[r];
}

__global__ void final_kernel(const float* __restrict__ log_gat,
                             const float* __restrict__ log_hmm,
                             const int* __restrict__ labels,
                             float* __restrict__ outLogits)
{
    int r = blockIdx.x * 256 + threadIdx.x;
    float lg[NCLS];
#pragma unroll
    for (int k = 0; k < NCLS; k++) {
        lg[k] = logf(0.5f * (log_gat[r * NCLS + k] + log_hmm[r * NCLS + k]));
        outLogits[r * NCLS + k] = lg[k];
    }
    int lab = labels[r];
    float picked = (lab >= 0) ? lg[lab] : 0.f;
    for (int o = 16; o > 0; o >>= 1) picked += __shfl_down_sync(0xffffffffu, picked, o);
    __shared__ float sh[8];
    if ((threadIdx.x & 31) == 0) sh[threadIdx.x >> 5] = picked;
    __syncthreads();
    if (threadIdx.x == 0) {
        float s = 0.f;
        for (int k = 0; k < 8; k++) s += sh[k];
        g_blocksums[blockIdx.x] = s;
    }
}

__global__ void finalize_kernel(float* d_out, int has_loss)
{
    if (has_loss) {
        float s = 0.f;
        for (int k = 0; k < 32; k++) s += g_blocksums[k];
        d_out[0] = -s / (float)ROWS;
    }
}

// ---------------- host launch ----------------
template <typename T>
static T* sym(const void* symbol)
{
    void* p = nullptr;
    cudaGetSymbolAddress(&p, symbol);
    return (T*)p;
}

static void gemm_tc(const bf16* A, float* C, bf16* Cbf, const bf16* Bt,
                    const float* bias, int dotanh,
                    const bf16* A2 = nullptr, float* C2 = nullptr, bf16* Cbf2 = nullptr)
{
    dim3 grid(Hh / BN, ROWS / BM, A2 ? 2 : 1);
    mma_gemm<<<grid, 256, GEMM_SMEM>>>(A, A2 ? A2 : A, C, C2 ? C2 : C,
                                       Cbf, Cbf2, Bt, bias, dotanh, Hh / BKg);
}

extern "C" void kernel_launch(void* const* d_in, const int* in_sizes, int n_in,
                              void* d_out, int out_size)
{
    (void)in_sizes; (void)n_in;
    const float* hidden_cls = (const float*)d_in[0];
    const float* hidden_emo = (const float*)d_in[1];
    const int*   labels     = (const int*)d_in[3];
    const float* pooler_W   = (const float*)d_in[4];
    const float* pooler_b   = (const float*)d_in[5];
    const float* gat_W      = (const float*)d_in[6];
    const float* gat_a1     = (const float*)d_in[7];
    const float* gat_a2     = (const float*)d_in[8];
    const float* out_W      = (const float*)d_in[9];
    const float* out_a1     = (const float*)d_in[10];
    const float* out_a2     = (const float*)d_in[11];
    const float* lin1_W     = (const float*)d_in[12];
    const float* lin1_b     = (const float*)d_in[13];
    const float* lin0_W     = (const float*)d_in[14];
    const float* lin0_b     = (const float*)d_in[15];
    const float* cls_W      = (const float*)d_in[16];
    const float* cls_b      = (const float*)d_in[17];
    const float* hmm_A      = (const float*)d_in[18];

    float* fea_cls = sym<float>(g_fea_cls);
    float* fea_emo = sym<float>(g_fea_emo);
    float* Wh      = sym<float>(g_Wh);
    float* Wh2     = sym<float>(g_Wh2);
    float* h2      = sym<float>(g_h2);
    float* s1b     = sym<float>(g_s1b);
    float* s2b     = sym<float>(g_s2b);
    float* mean1   = sym<float>(g_mean1);
    float* loggat  = sym<float>(g_loggat);
    float* Bprob   = sym<float>(g_Bprob);
    float* loghmm  = sym<float>(g_loghmm);
    bf16* hidcbf   = sym<bf16>(g_hid_cls_bf);
    bf16* hidebf   = sym<bf16>(g_hid_emo_bf);
    bf16* feacbf   = sym<bf16>(g_fea_cls_bf);
    bf16* h1bf     = sym<bf16>(g_h1_bf);
    bf16* poolWt   = sym<bf16>(g_poolWt);
    bf16* Wgt      = sym<bf16>(g_Wgt);
    bf16* outWt    = sym<bf16>(g_outWt);
    float* U0t     = sym<float>(g_U0t);
    float* U1t     = sym<float>(g_U1t);
    float* U2t     = sym<float>(g_U2t);
    float* cvec    = sym<float>(g_cvec);

    cudaFuncSetAttribute(mma_gemm, cudaFuncAttributeMaxDynamicSharedMemorySize, GEMM_SMEM);

    int has_loss = (out_size == ROWS * NCLS + 1) ? 1 : 0;
    float* outLogits = has_loss ? ((float*)d_out + 1) : (float*)d_out;

    // 0) weight prep + input converts + classifier folding
    {
        dim3 blk(32, 8);
        transpose_bf_kernel<<<dim3(Hh / 32, Hh / 32), blk>>>(pooler_W, poolWt, Hh, Hh);
        transpose_bf_kernel<<<dim3(Hh / 32, Hh / 32), blk>>>(out_W, outWt, Hh, Hh);
        repack_gatWt_kernel<<<(Hh * Hh) / 256, 256>>>(gat_W, Wgt);
        cvt_bf_kernel<<<dim3(ROWS * Hh / 1024, 2), 256>>>(hidden_cls, hidden_emo, hidcbf, hidebf);
        fold_u_kernel<<<2 * Hh, 224>>>(lin0_W, cls_W, U0t, U1t);
        fold_u2_kernel<<<Hh, 224>>>(lin1_W, U1t, U2t);
        fold_cvec_kernel<<<1, 224>>>(lin0_b, lin1_b, cls_W, cls_b, U1t, cvec);
    }

    // 1) poolers (tanh + bias), z-batched; fea_cls also emitted as bf16
    gemm_tc(hidcbf, fea_cls, feacbf, poolWt, pooler_b, 1, hidebf, fea_emo, nullptr);

    // 2) GAT layer 1 (scores fused into att1)
    gemm_tc(feacbf, Wh, nullptr, Wgt, nullptr, 0);
    mean_rows_kernel<<<dim3(Hh / 256, Bc), 256>>>(Wh, mean1);
    att1_tile_kernel<<<dim3(8, 8, Bc), 128>>>(Wh, gat_a1, gat_a2, h1bf);
    att1_row0_kernel<<<Bc, 256>>>(mean1, h1bf);

    // 3) GAT out layer
    gemm_tc(h1bf, Wh2, nullptr, outWt, nullptr, 0);
    out_scores_kernel<<<ROWS, 256>>>(Wh2, out_a1, out_a2, s1b, s2b);
    att2_tile_kernel<<<dim3(8, 8, Bc), 128>>>(Wh2, s1b, s2b, h2);

    // 4) folded classifier head
    gat_logits_kernel<<<ROWS, 224>>>(fea_cls, h2, U0t, U2t, cvec, loggat);

    // 5) HMM emission probs
    cls_softmax_kernel<<<ROWS, 224>>>(fea_emo, cls_W, cls_b, Bprob);

    // 6) HMM band filter
    hmm_kernel<<<ROWS / 128, 128>>>(Bprob, hmm_A, loghmm);

    // 7) final logits + loss
    final_kernel<<<ROWS / 256, 256>>>(loggat, loghmm, labels, outLogits);
    finalize_kernel<<<1, 1>>>((float*)d_out, has_loss);
}

// round 10
// speedup vs baseline: 1.5474x; 1.0017x over previous
#include <cuda_runtime.h>
#include <cuda_bf16.h>
#include <math.h>
#include <stdint.h>

// Problem constants
#define Bc   32
#define Nn   256
#define Hh   1024
#define HEADS 8
#define NHID 128
#define NCLS 7
#define BAND 24
#define ROWS (Bc*Nn)          // 8192
#define ALPHA_LRELU 0.2f

typedef __nv_bfloat16 bf16;

// ---------------- device scratch (no allocs allowed) ----------------
__device__ float g_s1b[ROWS];
__device__ float g_s2b[ROWS];
__device__ float g_mean1[Bc*Hh];
__device__ float g_loggat[ROWS*NCLS];
__device__ float g_Bprob[ROWS*NCLS];
__device__ float g_loghmm[ROWS*NCLS];
__device__ float g_blocksums[32];
// bf16 tensors
__device__ bf16 g_hid_cls_bf[ROWS*Hh];
__device__ bf16 g_hid_emo_bf[ROWS*Hh];
__device__ bf16 g_fea_cls_bf[ROWS*Hh];
__device__ bf16 g_fea_emo_bf[ROWS*Hh];
__device__ bf16 g_Wh_bf[ROWS*Hh];
__device__ bf16 g_Wh2_bf[ROWS*Hh];
__device__ bf16 g_h1_bf[ROWS*Hh];
__device__ bf16 g_h2_bf[ROWS*Hh];
__device__ bf16 g_poolWt[Hh*Hh];   // [N][K] k-major
__device__ bf16 g_Wgt[Hh*Hh];
__device__ bf16 g_outWt[Hh*Hh];
// folded classifier tables
__device__ float g_U0t[NCLS*Hh];
__device__ float g_U1t[NCLS*Hh];
__device__ float g_U2t[NCLS*Hh];
__device__ float g_cvec[NCLS];

// =================== bf16 mma.sync GEMM (4-stage cp.async pipeline) ==========
#define BM 128
#define BN 128
#define BKg 32
#define GSTG 4
#define APITCH 40                             // halves per smem row (80 B)
#define STAGE_BYTES (2 * BM * APITCH * 2)     // A + B = 20480 B
#define GEMM_SMEM (GSTG * STAGE_BYTES)        // 81920 B

__device__ __forceinline__ uint32_t smem_u32(const void* p) {
    uint32_t a;
    asm("{ .reg .u64 t; cvta.to.shared.u64 t, %1; cvt.u32.u64 %0, t; }" : "=r"(a) : "l"(p));
    return a;
}
__device__ __forceinline__ void cp16(uint32_t s, const void* g) {
    asm volatile("cp.async.cg.shared.global [%0], [%1], 16;" :: "r"(s), "l"(g));
}
#define CP_COMMIT() asm volatile("cp.async.commit_group;" ::: "memory")
#define CP_WAIT2()  asm volatile("cp.async.wait_group 2;" ::: "memory")

__device__ __forceinline__ void ldsm4(uint32_t& r0, uint32_t& r1, uint32_t& r2, uint32_t& r3,
                                      uint32_t addr) {
    asm volatile("ldmatrix.sync.aligned.m8n8.x4.shared.b16 {%0,%1,%2,%3}, [%4];"
                 : "=r"(r0), "=r"(r1), "=r"(r2), "=r"(r3) : "r"(addr));
}
__device__ __forceinline__ void mma_bf16(float& d0, float& d1, float& d2, float& d3,
                                         uint32_t a0, uint32_t a1, uint32_t a2, uint32_t a3,
                                         uint32_t b0, uint32_t b1) {
    asm volatile("mma.sync.aligned.m16n8k16.row.col.f32.bf16.bf16.f32 "
                 "{%0,%1,%2,%3}, {%4,%5,%6,%7}, {%8,%9}, {%0,%1,%2,%3};"
                 : "+f"(d0), "+f"(d1), "+f"(d2), "+f"(d3)
                 : "r"(a0), "r"(a1), "r"(a2), "r"(a3), "r"(b0), "r"(b1));
}

__device__ __forceinline__ void gemm_load_stage(uint32_t sb, int stage, int tid,
                                                const bf16* Ag, const bf16* Bg) {
    uint32_t abase = sb + stage * STAGE_BYTES;
    uint32_t bbase = abase + BM * APITCH * 2;
#pragma unroll
    for (int i = 0; i < 2; i++) {
        int idx = tid + 256 * i;
        int r = idx >> 2;
        int q = idx & 3;
        cp16(abase + r * (APITCH * 2) + q * 16, Ag + (size_t)r * Hh + q * 8);
        cp16(bbase + r * (APITCH * 2) + q * 16, Bg + (size_t)r * Hh + q * 8);
    }
}

// z-batched: blockIdx.z selects (Aa,Ca) or (Ab,Cb). B shared. bf16 output only.
__global__ void __launch_bounds__(256, 2)
mma_gemm(const bf16* __restrict__ Aa, const bf16* __restrict__ Ab,
         bf16* __restrict__ Ca, bf16* __restrict__ Cb,
         const bf16* __restrict__ Bt,
         const float* __restrict__ bias, int dotanh, int T)
{
    extern __shared__ char smem[];
    uint32_t sb = smem_u32(smem);
    const int tid = threadIdx.x;
    const int wid = tid >> 5, lane = tid & 31;
    const int wm = wid >> 2, wn = wid & 3;   // 2x4 warp grid, warp tile 64x32
    const int n0 = blockIdx.x * BN;
    const size_t m0 = (size_t)blockIdx.y * BM;
    const bf16* A = (blockIdx.z == 0) ? Aa : Ab;
    bf16* C = (blockIdx.z == 0) ? Ca : Cb;

    float acc[4][4][4];
#pragma unroll
    for (int mi = 0; mi < 4; mi++)
#pragma unroll
        for (int ni = 0; ni < 4; ni++)
#pragma unroll
            for (int k = 0; k < 4; k++) acc[mi][ni][k] = 0.f;

    const bf16* Arow = A + m0 * Hh;
    const bf16* Brow = Bt + (size_t)n0 * Hh;

    gemm_load_stage(sb, 0, tid, Arow, Brow);
    CP_COMMIT();
    gemm_load_stage(sb, 1, tid, Arow + BKg, Brow + BKg);
    CP_COMMIT();
    gemm_load_stage(sb, 2, tid, Arow + 2 * BKg, Brow + 2 * BKg);
    CP_COMMIT();

    const int tl = lane >> 3;          // ldmatrix tile selector
    const int l7 = lane & 7;

    for (int t = 0; t < T; t++) {
        CP_WAIT2();
        __syncthreads();
        int nc = t + 3;
        if (nc < T)
            gemm_load_stage(sb, nc % GSTG, tid, Arow + nc * BKg, Brow + nc * BKg);
        CP_COMMIT();   // always commit to keep group counting sound

        uint32_t sA = sb + (t % GSTG) * STAGE_BYTES;
        uint32_t sB = sA + BM * APITCH * 2;
#pragma unroll
        for (int ks = 0; ks < 2; ks++) {
            uint32_t a[4][4];
#pragma unroll
            for (int mi = 0; mi < 4; mi++) {
                int row = wm * 64 + mi * 16 + (tl & 1) * 8 + l7;
                int col = ks * 16 + (tl >> 1) * 8;
                ldsm4(a[mi][0], a[mi][1], a[mi][2], a[mi][3],
                      sA + row * (APITCH * 2) + col * 2);
            }
            uint32_t bq[2][4];
#pragma unroll
            for (int nn = 0; nn < 2; nn++) {
                int row = wn * 32 + nn * 16 + (tl >> 1) * 8 + l7;
                int col = ks * 16 + (tl & 1) * 8;
                ldsm4(bq[nn][0], bq[nn][1], bq[nn][2], bq[nn][3],
                      sB + row * (APITCH * 2) + col * 2);
            }
#pragma unroll
            for (int mi = 0; mi < 4; mi++)
#pragma unroll
                for (int ni = 0; ni < 4; ni++)
                    mma_bf16(acc[mi][ni][0], acc[mi][ni][1], acc[mi][ni][2], acc[mi][ni][3],
                             a[mi][0], a[mi][1], a[mi][2], a[mi][3],
                             bq[ni >> 1][(ni & 1) * 2], bq[ni >> 1][(ni & 1) * 2 + 1]);
        }
    }

    const int lq = lane >> 2;
    const int lr = lane & 3;
#pragma unroll
    for (int mi = 0; mi < 4; mi++) {
        int row = (int)m0 + wm * 64 + mi * 16 + lq;
#pragma unroll
        for (int ni = 0; ni < 4; ni++) {
            int col = n0 + wn * 32 + ni * 8 + lr * 2;
            float b0 = 0.f, b1 = 0.f;
            if (bias) { b0 = bias[col]; b1 = bias[col + 1]; }
            float2 v0, v1;
            v0.x = acc[mi][ni][0] + b0; v0.y = acc[mi][ni][1] + b1;
            v1.x = acc[mi][ni][2] + b0; v1.y = acc[mi][ni][3] + b1;
            if (dotanh) {
                v0.x = tanhf(v0.x); v0.y = tanhf(v0.y);
                v1.x = tanhf(v1.x); v1.y = tanhf(v1.y);
            }
            __nv_bfloat162 w0, w1;
            w0.x = __float2bfloat16_rn(v0.x); w0.y = __float2bfloat16_rn(v0.y);
            w1.x = __float2bfloat16_rn(v1.x); w1.y = __float2bfloat16_rn(v1.y);
            *(__nv_bfloat162*)(C + (size_t)row * Hh + col) = w0;
            *(__nv_bfloat162*)(C + (size_t)(row + 8) * Hh + col) = w1;
        }
    }
}

// =================== weight prep / converts ===================
__global__ void transpose_bf_kernel(const float* __restrict__ in, bf16* __restrict__ out,
                                    int K, int N)
{
    __shared__ float tile[32][33];
    int k0 = blockIdx.y * 32, n0 = blockIdx.x * 32;
    int tx = threadIdx.x, ty = threadIdx.y;
    for (int r = ty; r < 32; r += 8) tile[r][tx] = in[(size_t)(k0 + r) * N + n0 + tx];
    __syncthreads();
    for (int r = ty; r < 32; r += 8)
        out[(size_t)(n0 + r) * K + k0 + tx] = __float2bfloat16_rn(tile[tx][r]);
}
__global__ void repack_gatWt_kernel(const float* __restrict__ gw, bf16* __restrict__ Wgt)
{
    int idx = blockIdx.x * 256 + threadIdx.x;
    int n = idx >> 10, f = idx & 1023;
    int h = n >> 7, d = n & 127;
    Wgt[idx] = __float2bfloat16_rn(gw[((size_t)(h << 10 | f)) * NHID + d]);
}
__global__ void cvt_bf_kernel(const float* __restrict__ a, const float* __restrict__ b,
                              bf16* __restrict__ oa, bf16* __restrict__ ob)
{
    const float* src = blockIdx.y ? b : a;
    bf16* dst = blockIdx.y ? ob : oa;
    int idx = (blockIdx.x * 256 + threadIdx.x) * 4;
    float4 v = *(const float4*)(src + idx);
    __nv_bfloat162 w0, w1;
    w0.x = __float2bfloat16_rn(v.x); w0.y = __float2bfloat16_rn(v.y);
    w1.x = __float2bfloat16_rn(v.z); w1.y = __float2bfloat16_rn(v.w);
    *(__nv_bfloat162*)(dst + idx) = w0;
    *(__nv_bfloat162*)(dst + idx + 2) = w1;
}

__global__ void fold_u_kernel(const float* __restrict__ lin0W,
                              const float* __restrict__ clsW,
                              float* __restrict__ U0t, float* __restrict__ U1t)
{
    int r = blockIdx.x;
    int c = threadIdx.x >> 5, l = threadIdx.x & 31;
    const float* row = lin0W + (size_t)r * Hh;
    float acc = 0.f;
    for (int k = l; k < Hh; k += 32) acc += row[k] * clsW[k * NCLS + c];
    for (int o = 16; o > 0; o >>= 1) acc += __shfl_down_sync(0xffffffffu, acc, o);
    if (l == 0) {
        if (r < Hh) U0t[c * Hh + r] = acc;
        else        U1t[c * Hh + (r - Hh)] = acc;
    }
}
__global__ void fold_u2_kernel(const float* __restrict__ lin1W,
                               const float* __restrict__ U1t,
                               float* __restrict__ U2t)
{
    int r = blockIdx.x;
    int c = threadIdx.x >> 5, l = threadIdx.x & 31;
    const float* row = lin1W + (size_t)r * Hh;
    const float* u1 = U1t + c * Hh;
    float acc = 0.f;
    for (int k = l; k < Hh; k += 32) acc += row[k] * u1[k];
    for (int o = 16; o > 0; o >>= 1) acc += __shfl_down_sync(0xffffffffu, acc, o);
    if (l == 0) U2t[c * Hh + r] = acc;
}
__global__ void fold_cvec_kernel(const float* __restrict__ lin0b,
                                 const float* __restrict__ lin1b,
                                 const float* __restrict__ clsW,
                                 const float* __restrict__ clsb,
                                 const float* __restrict__ U1t,
                                 float* __restrict__ cvec)
{
    int c = threadIdx.x >> 5, l = threadIdx.x & 31;
    float acc = 0.f;
    for (int k = l; k < Hh; k += 32)
        acc += lin0b[k] * clsW[k * NCLS + c] + lin1b[k] * U1t[c * Hh + k];
    for (int o = 16; o > 0; o >>= 1) acc += __shfl_down_sync(0xffffffffu, acc, o);
    if (l == 0) cvec[c] = acc + clsb[c];
}

// =================== small kernels ===================
// column means of bf16 Wh per batch
__global__ void mean_rows_kernel(const bf16* __restrict__ X, float* __restrict__ out)
{
    int b = blockIdx.y;
    int c = blockIdx.x * 256 + threadIdx.x;
    const bf16* p = X + (size_t)b * Nn * Hh + c;
    float s = 0.f;
    for (int n = 0; n < Nn; n++) s += __bfloat162float(p[(size_t)n * Hh]);
    out[b * Hh + c] = s * (1.0f / Nn);
}

__device__ __forceinline__ float eluf(float x) { return x > 0.f ? x : expf(x) - 1.0f; }

// band attention layer 1 (per-head) with fused score computation. bf16 in/out.
__global__ void att1_tile_kernel(const bf16* __restrict__ Wh,
                                 const float* __restrict__ gat_a1,
                                 const float* __restrict__ gat_a2,
                                 bf16* __restrict__ h1)
{
    __shared__ float sW[55][128];
    __shared__ float sc1[55], sc2[55];
    __shared__ float sw[32][24];
    int b = blockIdx.z, h = blockIdx.y, it = blockIdx.x;
    int i0 = it * 32;
    int jlo0 = i0 - 23; if (jlo0 < 0) jlo0 = 0;
    int nrows = (i0 + 31) - jlo0 + 1;          // <= 55
    int tid = threadIdx.x;
    int warp = tid >> 5, lane = tid & 31;
    const bf16* base = Wh + (size_t)b * Nn * Hh + h * NHID;
    for (int rr = 0; rr < nrows; rr++)
        sW[rr][tid] = __bfloat162float(base[(size_t)(jlo0 + rr) * Hh + tid]);
    __syncthreads();
    {
        float a1v[4], a2v[4];
#pragma unroll
        for (int t = 0; t < 4; t++) {
            a1v[t] = gat_a1[h * NHID + lane + 32 * t];
            a2v[t] = gat_a2[h * NHID + lane + 32 * t];
        }
        for (int rr = warp; rr < nrows; rr += 4) {
            float d1 = 0.f, d2 = 0.f;
#pragma unroll
            for (int t = 0; t < 4; t++) {
                float v = sW[rr][lane + 32 * t];
                d1 += v * a1v[t];
                d2 += v * a2v[t];
            }
            for (int o = 16; o > 0; o >>= 1) {
                d1 += __shfl_down_sync(0xffffffffu, d1, o);
                d2 += __shfl_down_sync(0xffffffffu, d2, o);
            }
            if (lane == 0) { sc1[rr] = d1; sc2[rr] = d2; }
        }
    }
    __syncthreads();
    if (tid < 32) {
        int i = i0 + tid;
        if (i > 0) {
            int jl = i - 23; if (jl < 0) jl = 0;
            int L = i - jl;
            float si = sc1[i - jlo0];
            float mx = -1e30f;
            for (int t = 0; t < L; t++) {
                float v = si + sc2[jl + t - jlo0];
                v = v > 0.f ? v : ALPHA_LRELU * v;
                sw[tid][t] = v; mx = fmaxf(mx, v);
            }
            float ssum = 0.f;
            for (int t = 0; t < L; t++) { float ex = expf(sw[tid][t] - mx); sw[tid][t] = ex; ssum += ex; }
            float inv = 1.0f / ssum;
            for (int t = 0; t < L; t++) sw[tid][t] *= inv;
        }
    }
    __syncthreads();
    for (int il = 0; il < 32; il++) {
        int i = i0 + il;
        if (i == 0) continue;
        int jl = i - 23; if (jl < 0) jl = 0;
        int L = i - jl, roff = jl - jlo0;
        float acc = 0.f;
        for (int t = 0; t < L; t++) acc += sw[il][t] * sW[roff + t][tid];
        h1[((size_t)b * Nn + i) * Hh + h * NHID + tid] = __float2bfloat16_rn(eluf(acc));
    }
}

__global__ void att1_row0_kernel(const float* __restrict__ mean1, bf16* __restrict__ h1)
{
    int b = blockIdx.x;
    for (int c = threadIdx.x; c < Hh; c += 256)
        h1[(size_t)b * Nn * Hh + c] = __float2bfloat16_rn(eluf(mean1[b * Hh + c]));
}

__global__ void out_scores_kernel(const bf16* __restrict__ Wh2,
                                  const float* __restrict__ a1,
                                  const float* __restrict__ a2,
                                  float* __restrict__ s1, float* __restrict__ s2)
{
    int n = blockIdx.x;
    int tid = threadIdx.x;
    float x1 = 0.f, x2 = 0.f;
    const bf16* x = Wh2 + (size_t)n * Hh;
    for (int c = tid; c < Hh; c += 256) {
        float v = __bfloat162float(x[c]);
        x1 += v * a1[c]; x2 += v * a2[c];
    }
    __shared__ float sh1[8], sh2[8];
    for (int o = 16; o > 0; o >>= 1) {
        x1 += __shfl_down_sync(0xffffffffu, x1, o);
        x2 += __shfl_down_sync(0xffffffffu, x2, o);
    }
    if ((tid & 31) == 0) { sh1[tid >> 5] = x1; sh2[tid >> 5] = x2; }
    __syncthreads();
    if (tid == 0) {
        float t1 = 0.f, t2 = 0.f;
        for (int k = 0; k < 8; k++) { t1 += sh1[k]; t2 += sh2[k]; }
        s1[n] = t1; s2[n] = t2;
    }
}

__global__ void att2_tile_kernel(const bf16* __restrict__ Wh2,
                                 const float* __restrict__ s1,
                                 const float* __restrict__ s2,
                                 bf16* __restrict__ out)
{
    __shared__ float sW[54][128];
    __shared__ float sw[32][24];
    int b = blockIdx.z, ct = blockIdx.y, it = blockIdx.x;
    int i0 = it * 32, c0 = ct * 128;
    int jlo0 = i0 - 23; if (jlo0 < 0) jlo0 = 0;
    int nrows = (i0 + 30) - jlo0 + 1;
    int tid = threadIdx.x;
    const bf16* base = Wh2 + (size_t)b * Nn * Hh + c0;
    for (int rr = 0; rr < nrows; rr++)
        sW[rr][tid] = __bfloat162float(base[(size_t)(jlo0 + rr) * Hh + tid]);
    if (tid < 32) {
        int i = i0 + tid;
        if (i > 0) {
            int jl = i - 23; if (jl < 0) jl = 0;
            int L = i - jl;
            float si = s1[(size_t)b * Nn + i];
            float mx = -1e30f;
            for (int t = 0; t < L; t++) {
                float v = si + s2[(size_t)b * Nn + jl + t];
                v = v > 0.f ? v : ALPHA_LRELU * v;
                sw[tid][t] = v; mx = fmaxf(mx, v);
            }
            float ssum = 0.f;
            for (int t = 0; t < L; t++) { float ex = expf(sw[tid][t] - mx); sw[tid][t] = ex; ssum += ex; }
            float inv = 1.0f / ssum;
            for (int t = 0; t < L; t++) sw[tid][t] *= inv;
        }
    }
    __syncthreads();
    for (int il = 0; il < 32; il++) {
        int i = i0 + il;
        if (i == 0) continue;
        int jl = i - 23; if (jl < 0) jl = 0;
        int L = i - jl, roff = jl - jlo0;
        float acc = 0.f;
        for (int t = 0; t < L; t++) acc += sw[il][t] * sW[roff + t][tid];
        out[((size_t)b * Nn + i) * Hh + c0 + tid] = __float2bfloat16_rn(eluf(acc));
    }
}

__global__ void gat_logits_kernel(const bf16* __restrict__ fea_cls,
                                  const bf16* __restrict__ h2,
                                  const float* __restrict__ U0t,
                                  const float* __restrict__ U2t,
                                  const float* __restrict__ cvec,
                                  float* __restrict__ out)
{
    int n = blockIdx.x;
    int i = n & (Nn - 1);
    int c = threadIdx.x >> 5, l = threadIdx.x & 31;
    const bf16* frow = fea_cls + (size_t)n * Hh;
    const bf16* hrow = (i == 0) ? frow : h2 + (size_t)n * Hh;
    const float* u0 = U0t + c * Hh;
    const float* u2 = U2t + c * Hh;
    float acc = 0.f;
    for (int k = l; k < Hh; k += 32)
        acc += __bfloat162float(frow[k]) * u0[k] + __bfloat162float(hrow[k]) * u2[k];
    for (int o = 16; o > 0; o >>= 1) acc += __shfl_down_sync(0xffffffffu, acc, o);
    __shared__ float sh[NCLS];
    if (l == 0) sh[c] = acc + cvec[c];
    __syncthreads();
    if (threadIdx.x == 0) {
        float mx = sh[0];
        for (int k = 1; k < NCLS; k++) mx = fmaxf(mx, sh[k]);
        float e[NCLS], s = 0.f;
        for (int k = 0; k < NCLS; k++) { e[k] = expf(sh[k] - mx); s += e[k]; }
        float inv = 1.0f / s;
        for (int k = 0; k < NCLS; k++) out[n * NCLS + k] = e[k] * inv;
    }
}

__global__ void cls_softmax_kernel(const bf16* __restrict__ X,
                                   const float* __restrict__ W,
                                   const float* __restrict__ bcls,
                                   float* __restrict__ out)
{
    int n = blockIdx.x;
    int wid = threadIdx.x >> 5, l = threadIdx.x & 31;
    __shared__ float sh[NCLS];
    const bf16* x = X + (size_t)n * Hh;
    float acc = 0.f;
    for (int t = l; t < Hh; t += 32) acc += __bfloat162float(x[t]) * W[t * NCLS + wid];
    for (int o = 16; o > 0; o >>= 1) acc += __shfl_down_sync(0xffffffffu, acc, o);
    if (l == 0) sh[wid] = acc + bcls[wid];
    __syncthreads();
    if (threadIdx.x == 0) {
        float mx = sh[0];
        for (int k = 1; k < NCLS; k++) mx = fmaxf(mx, sh[k]);
        float e[NCLS], s = 0.f;
        for (int k = 0; k < NCLS; k++) { e[k] = expf(sh[k] - mx); s += e[k]; }
        float inv = 1.0f / s;
        for (int k = 0; k < NCLS; k++) out[n * NCLS + k] = e[k] * inv;
    }
}

__global__ void hmm_kernel(const float* __restrict__ Bprob,
                           const float* __restrict__ hmmA,
                           float* __restrict__ out)
{
    __shared__ float sAT[NCLS * NCLS];
    int tid = threadIdx.x;
    if (tid < NCLS * NCLS) sAT[tid] = hmmA[(tid % NCLS) * NCLS + (tid / NCLS)];
    __syncthreads();
    int gidx = blockIdx.x * 128 + tid;
    int b = gidx >> 8, i = gidx & 255;
    const float* Bp = Bprob + (size_t)b * Nn * NCLS;
    int t0 = i - (BAND - 1); if (t0 < 0) t0 = 0;
    float p[NCLS]; float s = 0.f;
#pragma unroll
    for (int r = 0; r < NCLS; r++) { p[r] = Bp[t0 * NCLS + r]; s += p[r]; }
    float inv = 1.0f / s;
#pragma unroll
    for (int r = 0; r < NCLS; r++) p[r] *= inv;
    for (int t = t0 + 1; t <= i; t++) {
        float q[NCLS]; s = 0.f;
#pragma unroll
        for (int r = 0; r < NCLS; r++) {
            float a = 0.f;
#pragma unroll
            for (int c = 0; c < NCLS; c++) a += sAT[r * NCLS + c] * p[c];
            a *= Bp[t * NCLS + r];
            q[r] = a; s += a;
        }
        inv = 1.0f / s;
#pragma unroll
        for (int r = 0; r < NCLS; r++) p[r] = q[r] * inv;
    }
#pragma unroll
    for (int r = 0; r < NCLS; r++) out[gidx * NCLS + r] = p[r];
}

__global__ void final_kernel(const float* __restrict__ log_gat,
                             const float* __restrict__ log_hmm,
                             const int* __restrict__ labels,
                             float* __restrict__ outLogits)
{
    int r = blockIdx.x * 256 + threadIdx.x;
    float lg[NCLS];
#pragma unroll
    for (int k = 0; k < NCLS; k++) {
        lg[k] = logf(0.5f * (log_gat[r * NCLS + k] + log_hmm[r * NCLS + k]));
        outLogits[r * NCLS + k] = lg[k];
    }
    int lab = labels[r];
    float picked = (lab >= 0) ? lg[lab] : 0.f;
    for (int o = 16; o > 0; o >>= 1) picked += __shfl_down_sync(0xffffffffu, picked, o);
    __shared__ float sh[8];
    if ((threadIdx.x & 31) == 0) sh[threadIdx.x >> 5] = picked;
    __syncthreads();
    if (threadIdx.x == 0) {
        float s = 0.f;
        for (int k = 0; k < 8; k++) s += sh[k];
        g_blocksums[blockIdx.x] = s;
    }
}

__global__ void finalize_kernel(float* d_out, int has_loss)
{
    if (has_loss) {
        float s = 0.f;
        for (int k = 0; k < 32; k++) s += g_blocksums[k];
        d_out[0] = -s / (float)ROWS;
    }
}

// ---------------- host launch ----------------
template <typename T>
static T* sym(const void* symbol)
{
    void* p = nullptr;
    cudaGetSymbolAddress(&p, symbol);
    return (T*)p;
}

static void gemm_tc(const bf16* A, bf16* C, const bf16* Bt,
                    const float* bias, int dotanh,
                    const bf16* A2 = nullptr, bf16* C2 = nullptr)
{
    dim3 grid(Hh / BN, ROWS / BM, A2 ? 2 : 1);
    mma_gemm<<<grid, 256, GEMM_SMEM>>>(A, A2 ? A2 : A, C, C2 ? C2 : C,
                                       Bt, bias, dotanh, Hh / BKg);
}

extern "C" void kernel_launch(void* const* d_in, const int* in_sizes, int n_in,
                              void* d_out, int out_size)
{
    (void)in_sizes; (void)n_in;
    const float* hidden_cls = (const float*)d_in[0];
    const float* hidden_emo = (const float*)d_in[1];
    const int*   labels     = (const int*)d_in[3];
    const float* pooler_W   = (const float*)d_in[4];
    const float* pooler_b   = (const float*)d_in[5];
    const float* gat_W      = (const float*)d_in[6];
    const float* gat_a1     = (const float*)d_in[7];
    const float* gat_a2     = (const float*)d_in[8];
    const float* out_W      = (const float*)d_in[9];
    const float* out_a1     = (const float*)d_in[10];
    const float* out_a2     = (const float*)d_in[11];
    const float* lin1_W     = (const float*)d_in[12];
    const float* lin1_b     = (const float*)d_in[13];
    const float* lin0_W     = (const float*)d_in[14];
    const float* lin0_b     = (const float*)d_in[15];
    const float* cls_W      = (const float*)d_in[16];
    const float* cls_b      = (const float*)d_in[17];
    const float* hmm_A      = (const float*)d_in[18];

    float* s1b     = sym<float>(g_s1b);
    float* s2b     = sym<float>(g_s2b);
    float* mean1   = sym<float>(g_mean1);
    float* loggat  = sym<float>(g_loggat);
    float* Bprob   = sym<float>(g_Bprob);
    float* loghmm  = sym<float>(g_loghmm);
    bf16* hidcbf   = sym<bf16>(g_hid_cls_bf);
    bf16* hidebf   = sym<bf16>(g_hid_emo_bf);
    bf16* feacbf   = sym<bf16>(g_fea_cls_bf);
    bf16* feaebf   = sym<bf16>(g_fea_emo_bf);
    bf16* Whbf     = sym<bf16>(g_Wh_bf);
    bf16* Wh2bf    = sym<bf16>(g_Wh2_bf);
    bf16* h1bf     = sym<bf16>(g_h1_bf);
    bf16* h2bf     = sym<bf16>(g_h2_bf);
    bf16* poolWt   = sym<bf16>(g_poolWt);
    bf16* Wgt      = sym<bf16>(g_Wgt);
    bf16* outWt    = sym<bf16>(g_outWt);
    float* U0t     = sym<float>(g_U0t);
    float* U1t     = sym<float>(g_U1t);
    float* U2t     = sym<float>(g_U2t);
    float* cvec    = sym<float>(g_cvec);

    cudaFuncSetAttribute(mma_gemm, cudaFuncAttributeMaxDynamicSharedMemorySize, GEMM_SMEM);

    int has_loss = (out_size == ROWS * NCLS + 1) ? 1 : 0;
    float* outLogits = has_loss ? ((float*)d_out + 1) : (float*)d_out;

    // 0) weight prep + input converts + classifier folding
    {
        dim3 blk(32, 8);
        transpose_bf_kernel<<<dim3(Hh / 32, Hh / 32), blk>>>(pooler_W, poolWt, Hh, Hh);
        transpose_bf_kernel<<<dim3(Hh / 32, Hh / 32), blk>>>(out_W, outWt, Hh, Hh);
        repack_gatWt_kernel<<<(Hh * Hh) / 256, 256>>>(gat_W, Wgt);
        cvt_bf_kernel<<<dim3(ROWS * Hh / 1024, 2), 256>>>(hidden_cls, hidden_emo, hidcbf, hidebf);
        fold_u_kernel<<<2 * Hh, 224>>>(lin0_W, cls_W, U0t, U1t);
        fold_u2_kernel<<<Hh, 224>>>(lin1_W, U1t, U2t);
        fold_cvec_kernel<<<1, 224>>>(lin0_b, lin1_b, cls_W, cls_b, U1t, cvec);
    }

    // 1) poolers (tanh + bias), z-batched; bf16 outputs
    gemm_tc(hidcbf, feacbf, poolWt, pooler_b, 1, hidebf, feaebf);

    // 2) GAT layer 1 (scores fused into att1)
    gemm_tc(feacbf, Whbf, Wgt, nullptr, 0);
    mean_rows_kernel<<<dim3(Hh / 256, Bc), 256>>>(Whbf, mean1);
    att1_tile_kernel<<<dim3(8, 8, Bc), 128>>>(Whbf, gat_a1, gat_a2, h1bf);
    att1_row0_kernel<<<Bc, 256>>>(mean1, h1bf);

    // 3) GAT out layer
    gemm_tc(h1bf, Wh2bf, outWt, nullptr, 0);
    out_scores_kernel<<<ROWS, 256>>>(Wh2bf, out_a1, out_a2, s1b, s2b);
    att2_tile_kernel<<<dim3(8, 8, Bc), 128>>>(Wh2bf, s1b, s2b, h2bf);

    // 4) folded classifier head
    gat_logits_kernel<<<ROWS, 224>>>(feacbf, h2bf, U0t, U2t, cvec, loggat);

    // 5) HMM emission probs
    cls_softmax_kernel<<<ROWS, 224>>>(feaebf, cls_W, cls_b, Bprob);

    // 6) HMM band filter
    hmm_kernel<<<ROWS / 128, 128>>>(Bprob, hmm_A, loghmm);

    // 7) final logits + loss
    final_kernel<<<ROWS / 256, 256>>>(loggat, loghmm, labels, outLogits);
    finalize_kernel<<<1, 1>>>((float*)d_out, has_loss);
}